// round 7
// baseline (speedup 1.0000x reference)
#include <cuda_runtime.h>
#include <math.h>
#include <stdint.h>

#define DD 200
#define NTY 4
#define NET 38
#define NT1 39
#define BB 256
#define LL 1024
#define EE 262144
#define NN 51200
#define NCOMBO 608
#define TOTROWS (EE + NN)

// f32x2 packed-math helpers
#define FMA2(d,a,b)  asm("fma.rn.f32x2 %0, %1, %2, %3;" : "=l"(d) : "l"(a), "l"(b), "l"(d))
#define PACK2(d,x,y) asm("mov.b64 %0, {%1, %2};" : "=l"(d) : "f"(x), "f"(y))
#define UNPACK2(x,y,d) asm("mov.b64 {%0, %1}, %2;" : "=f"(x), "=f"(y) : "l"(d))

#define CVT_TF32(u,f) asm("cvt.rna.tf32.f32 %0, %1;" : "=r"(u) : "f"(f))
#define MMA_TF32(c0,c1,c2,c3,a0,a1,a2,a3,b0,b1) \
  asm("mma.sync.aligned.m16n8k8.row.col.f32.tf32.tf32.f32 " \
      "{%0,%1,%2,%3},{%4,%5,%6,%7},{%8,%9},{%0,%1,%2,%3};" \
      : "+f"(c0),"+f"(c1),"+f"(c2),"+f"(c3) \
      : "r"(a0),"r"(a1),"r"(a2),"r"(a3),"r"(b0),"r"(b1))

// ------------------------- scratch -------------------------
__device__ float d_coeff[(size_t)NN * NT1];
__device__ float d_sums[NT1 * DD];
__device__ int   d_cntT[NT1];
__device__ int   d_cntE[NCOMBO];
__device__ int   d_cntN[NTY];
__device__ int   d_combo[EE];
__device__ int   d_cntSrc[NN];
__device__ int   d_dstCnt[NN];
__device__ int   d_dstOff[NN + 1];
__device__ int   d_srcOff[NN + 1];
__device__ int   d_cursorD[NN];
__device__ int   d_cursorS[NN];
__device__ int   d_csr[TOTROWS];
__device__ int   d_csrS[TOTROWS];
__device__ int   d_blkSum[2][50];
__device__ float d_meanT[NT1 * DD];
__device__ float d_preAll[640 * DD];
__device__ float d_embAll[640 * DD];
__device__ float d_A2[640 * 400];
__device__ float d_h2All[640 * DD];
__device__ float d_RtabP[640 * 256];
__device__ float d_RtabT[DD * 640];
__device__ float d_qmat[BB * DD];
__device__ float d_P[BB * 640];
__device__ float d_Wt[BB * 640];
__device__ float d_S[384 * DD];        // rows 0..255 = upd, 256..259 = embS
__device__ float d_UKM[260 * 400];     // per row: [UK(200) | UM(200)]
__device__ float d_bn1m[DD], d_bn1r[DD], d_bn2m[DD], d_bn2r[DD], d_bn3m[DD], d_bn3r[DD];
__device__ float d_Wcat[DD * 640];
__device__ float d_bcat[640];
__device__ float d_Wo1P[DD * 256];
__device__ float d_Wo2P[DD * 256];
__device__ float d_We2P[DD * 256];
__device__ float d_Wa1P[400 * 256];
__device__ float d_Wa2P[DD * 256];
__device__ float d_WattP[DD * 256];
__device__ float d_WkmP[DD * 512];
__device__ float d_XKMQ[(size_t)NN * 600];    // per-node [XK+bk | XM+bm | (XQ+bq)*invs]
__device__ float d_ex[(size_t)TOTROWS * 4];
__device__ float d_den[NN * 4];
__device__ float d_aggr[(size_t)NN * DD];
__device__ float d_Y1[(size_t)NN * DD];
__device__ float d_colsum[DD], d_colsum2[DD];

// ------------------------- zero init + node hist (fused) -------------------------
__global__ void k_zero(const int* __restrict__ ntp) {
    long long i0 = (long long)blockIdx.x * blockDim.x + threadIdx.x;
    long long st = (long long)gridDim.x * blockDim.x;
    for (long long i = i0; i < (long long)NT1 * NN; i += st) d_coeff[i] = 0.f;
    for (long long i = i0; i < NT1 * DD; i += st) d_sums[i] = 0.f;
    for (long long i = i0; i < NCOMBO; i += st) d_cntE[i] = 0;
    for (long long i = i0; i < NT1; i += st) d_cntT[i] = 0;
    for (long long i = i0; i < NTY; i += st) d_cntN[i] = 0;
    for (long long i = i0; i < DD; i += st) { d_colsum[i] = 0.f; d_colsum2[i] = 0.f; }
    for (long long i = i0; i < 640 * DD; i += st) { d_preAll[i] = 0.f; d_h2All[i] = 0.f; }
    for (long long i = i0; i < 640 * 400; i += st) d_A2[i] = 0.f;
    for (long long i = i0; i < 640 * 256; i += st) d_RtabP[i] = 0.f;
    for (long long i = i0; i < 384 * DD; i += st) d_S[i] = 0.f;
    for (long long i = i0; i < NN; i += st) {
        d_cntSrc[i] = 1;
        d_dstCnt[i] = 1;
        atomicAdd(&d_cntN[ntp[i]], 1);
    }
}

__global__ void k_edgehist(const int* __restrict__ ei, const int* __restrict__ et,
                           const int* __restrict__ ntp) {
    int e = blockIdx.x * blockDim.x + threadIdx.x;
    if (e >= EE) return;
    int s  = ei[e];
    int dd = ei[EE + e];
    int t  = et[e];
    atomicAdd(&d_coeff[(size_t)dd * NT1 + t],  1.f);
    atomicAdd(&d_coeff[(size_t)s  * NT1 + t], -1.f);
    atomicAdd(&d_cntT[t], 1);
    int c = (t << 4) | (ntp[s] << 2) | ntp[dd];
    d_combo[e] = c;
    atomicAdd(&d_cntE[c], 1);
    atomicAdd(&d_cntSrc[s], 1);
    atomicAdd(&d_dstCnt[dd], 1);
}

// ------------------------- dual CSR build (dst + src), 3-phase scan -------------------------
__global__ void k_scanA2() {                 // grid (50,2)
    __shared__ int sm[1024];
    int tid = threadIdx.x;
    const int* cnt = blockIdx.y ? d_cntSrc : d_dstCnt;
    sm[tid] = cnt[blockIdx.x * 1024 + tid];
    __syncthreads();
    for (int o = 512; o > 0; o >>= 1) {
        if (tid < o) sm[tid] += sm[tid + o];
        __syncthreads();
    }
    if (tid == 0) d_blkSum[blockIdx.y][blockIdx.x] = sm[0];
}

__global__ void k_scanB2() {                 // 2 blocks x 64
    __shared__ int sm[64];
    int y = blockIdx.x;
    int tid = threadIdx.x;
    int v = (tid < 50) ? d_blkSum[y][tid] : 0;
    sm[tid] = v;
    __syncthreads();
    for (int o = 1; o < 64; o <<= 1) {
        int t = (tid >= o) ? sm[tid - o] : 0;
        __syncthreads();
        sm[tid] += t;
        __syncthreads();
    }
    if (tid < 50) d_blkSum[y][tid] = sm[tid] - v;
    if (tid == 49) { if (y) d_srcOff[NN] = sm[49]; else d_dstOff[NN] = sm[49]; }
}

__global__ void k_scanC2() {                 // grid (50,2)
    __shared__ int sm[1024];
    int tid = threadIdx.x;
    int y = blockIdx.y;
    int g = blockIdx.x * 1024 + tid;
    int v = y ? d_cntSrc[g] : d_dstCnt[g];
    sm[tid] = v;
    __syncthreads();
    for (int o = 1; o < 1024; o <<= 1) {
        int t = (tid >= o) ? sm[tid - o] : 0;
        __syncthreads();
        sm[tid] += t;
        __syncthreads();
    }
    int excl = sm[tid] - v + d_blkSum[y][blockIdx.x];
    if (y) { d_srcOff[g] = excl; d_cursorS[g] = excl; }
    else   { d_dstOff[g] = excl; d_cursorD[g] = excl; }
}

__global__ void k_csrfill(const int* __restrict__ ei) {
    int i = blockIdx.x * blockDim.x + threadIdx.x;
    if (i >= TOTROWS) return;
    int dst = (i < EE) ? ei[EE + i] : (i - EE);
    d_csr[atomicAdd(&d_cursorD[dst], 1)] = i;
    int src = (i < EE) ? ei[i] : (i - EE);
    d_csrS[atomicAdd(&d_cursorS[src], 1)] = i;
}

// ------------------------- segment sums -------------------------
__global__ __launch_bounds__(128) void k_segsum3(const float* __restrict__ x) {
    __shared__ unsigned long long cf2[128][NT1];
    int tid = threadIdx.x;
    int n0 = blockIdx.x * 128;
    for (int i = tid; i < 128 * NT1; i += 128) {
        float c = d_coeff[(size_t)(n0 + i / NT1) * NT1 + (i % NT1)];
        unsigned long long c2; PACK2(c2, c, c);
        cf2[i / NT1][i % NT1] = c2;
    }
    __syncthreads();
    if (tid < 100) {
        unsigned long long acc[NT1];
#pragma unroll
        for (int t = 0; t < NT1; t++) acc[t] = 0ULL;
        for (int nn = 0; nn < 128; nn++) {
            float2 xv = *(const float2*)&x[(size_t)(n0 + nn) * DD + tid * 2];
            unsigned long long xv2; PACK2(xv2, xv.x, xv.y);
#pragma unroll
            for (int t = 0; t < NT1; t++)
                FMA2(acc[t], cf2[nn][t], xv2);
        }
#pragma unroll
        for (int t = 0; t < NT1; t++) {
            float lo, hi; UNPACK2(lo, hi, acc[t]);
            if (lo != 0.f) atomicAdd(&d_sums[t * DD + tid * 2], lo);
            if (hi != 0.f) atomicAdd(&d_sums[t * DD + tid * 2 + 1], hi);
        }
    }
}

__global__ void k_meanT() {
    int i = blockIdx.x * blockDim.x + threadIdx.x;
    if (i >= NT1 * DD) return;
    int t = i / DD;
    float c = (float)d_cntT[t];
    if (c < 1.f) c = 1.f;
    d_meanT[i] = d_sums[i] / c;
}

// ------------------------- combo tables -------------------------
__global__ void k_tables(const float* __restrict__ We1, const float* __restrict__ be1) {
    int c = blockIdx.x, d = threadIdx.x;
    if (d >= DD) return;
    if (c < NCOMBO) {
        int t = c >> 4, a = (c >> 2) & 3, b = c & 3;
        d_preAll[c * DD + d] = We1[t * DD + d] + We1[(NT1 + a) * DD + d]
                             + We1[(NT1 + NTY + b) * DD + d] + be1[d];
    } else {
        int t = c - NCOMBO;
        d_preAll[(NCOMBO + t) * DD + d] = We1[NET * DD + d] + We1[(NT1 + t) * DD + d]
                                        + We1[(NT1 + NTY + t) * DD + d] + be1[d];
    }
}

__global__ void k_bnstat1p() {
    int d = blockIdx.x, tid = threadIdx.x;
    __shared__ double rs[128], rs2[128];
    double s = 0.0, s2 = 0.0;
    for (int c = tid; c < NCOMBO; c += 128) {
        double w = (double)d_cntE[c], v = (double)d_preAll[c * DD + d];
        s += w * v; s2 += w * v * v;
    }
    if (tid < NTY) {
        double w = (double)d_cntN[tid], v = (double)d_preAll[(NCOMBO + tid) * DD + d];
        s += w * v; s2 += w * v * v;
    }
    rs[tid] = s; rs2[tid] = s2;
    __syncthreads();
    for (int o = 64; o > 0; o >>= 1) {
        if (tid < o) { rs[tid] += rs[tid + o]; rs2[tid] += rs2[tid + o]; }
        __syncthreads();
    }
    if (tid == 0) {
        double m = rs[0] / (double)TOTROWS;
        double var = rs2[0] / (double)TOTROWS - m * m;
        d_bn1m[d] = (float)m;
        d_bn1r[d] = rsqrtf((float)var + 1e-5f);
    }
}

__global__ void k_bnstat2p() {
    int d = blockIdx.x, tid = threadIdx.x;
    __shared__ double rs[128], rs2[128];
    double s = 0.0, s2 = 0.0;
    for (int c = tid; c < NCOMBO; c += 128) {
        double w = (double)d_cntE[c], v = (double)d_h2All[c * DD + d];
        s += w * v; s2 += w * v * v;
    }
    rs[tid] = s; rs2[tid] = s2;
    __syncthreads();
    for (int o = 64; o > 0; o >>= 1) {
        if (tid < o) { rs[tid] += rs[tid + o]; rs2[tid] += rs2[tid + o]; }
        __syncthreads();
    }
    if (tid == 0) {
        double m = rs[0] / (double)EE;
        double var = rs2[0] / (double)EE - m * m;
        d_bn2m[d] = (float)m;
        d_bn2r[d] = rsqrtf((float)var + 1e-5f);
    }
}

// ------------------------- glue kernels -------------------------
__global__ void k_buildA2() {
    int c = blockIdx.x, t = threadIdx.x;
    if (t < DD)       d_A2[c * 400 + t] = d_embAll[c * DD + t];
    else if (t < 400) d_A2[c * 400 + t] = d_meanT[(c >> 4) * DD + (t - DD)];
}

__global__ void k_transT() {   // RtabT[k][c] = RtabP[c][k]; plus copy embS rows into d_S
    int i = blockIdx.x * blockDim.x + threadIdx.x;
    if (i < DD * 640) {
        int k = i / 640, c = i % 640;
        d_RtabT[i] = (c < NCOMBO) ? d_RtabP[c * 256 + k] : 0.f;
        return;
    }
    i -= DD * 640;
    if (i < NTY * DD) {
        int r = i / DD, c = i % DD;
        d_S[(BB + r) * DD + c] = d_embAll[(NCOMBO + r) * DD + c];
    }
}

// softmax over each graph's 1024 edges -> per-combo weight mass Wt
__global__ __launch_bounds__(256) void k_attnP() {
    int b = blockIdx.x, tid = threadIdx.x;
    __shared__ float Pb[NCOMBO], Wacc[NCOMBO];
    __shared__ float red[256];
    for (int i = tid; i < NCOMBO; i += 256) { Pb[i] = d_P[b * 640 + i]; Wacc[i] = 0.f; }
    __syncthreads();
    int cid[4]; float sc[4]; float lmax = -1e30f;
#pragma unroll
    for (int j = 0; j < 4; j++) {
        int e = b * LL + tid + j * 256;
        cid[j] = d_combo[e];
        sc[j] = Pb[cid[j]];
        lmax = fmaxf(lmax, sc[j]);
    }
    red[tid] = lmax; __syncthreads();
    for (int s = 128; s > 0; s >>= 1) { if (tid < s) red[tid] = fmaxf(red[tid], red[tid + s]); __syncthreads(); }
    float bmax = red[0]; __syncthreads();
    float lsum = 0.f;
#pragma unroll
    for (int j = 0; j < 4; j++) { sc[j] = expf(sc[j] - bmax); lsum += sc[j]; }
    red[tid] = lsum; __syncthreads();
    for (int s = 128; s > 0; s >>= 1) { if (tid < s) red[tid] += red[tid + s]; __syncthreads(); }
    float inv = 1.f / red[0]; __syncthreads();
#pragma unroll
    for (int j = 0; j < 4; j++) atomicAdd(&Wacc[cid[j]], sc[j] * inv);
    __syncthreads();
    for (int i = tid; i < 640; i += 256)
        d_Wt[b * 640 + i] = (i < NCOMBO) ? Wacc[i] : 0.f;
}

// ------------------------- weight packing -------------------------
__global__ void k_pack(const float* __restrict__ Wk, const float* __restrict__ Wm,
                       const float* __restrict__ Wq,
                       const float* __restrict__ bk, const float* __restrict__ bm,
                       const float* __restrict__ bq,
                       const float* __restrict__ Wo1, const float* __restrict__ Wo2,
                       const float* __restrict__ We2, const float* __restrict__ Wa1,
                       const float* __restrict__ Wa2, const float* __restrict__ Watt) {
    const float invs = 0.1414213562373095f;   // 1/sqrt(50)
    const float qsc  = 0.07071067811865475f;  // 1/sqrt(200)
    int i = blockIdx.x * blockDim.x + threadIdx.x;
    if (i < DD * 640) {
        int k = i / 640, c = i % 640;
        d_Wcat[i] = (c < DD) ? Wk[k * DD + c]
                  : (c < 2 * DD) ? Wm[k * DD + (c - DD)]
                  : (c < 3 * DD) ? Wq[k * DD + (c - 2 * DD)] * invs : 0.f;
        return;
    }
    i -= DD * 640;
    if (i < DD * 256) { int k = i >> 8, c = i & 255; d_Wo1P[i] = (c < DD) ? Wo1[k * DD + c] : 0.f; return; }
    i -= DD * 256;
    if (i < DD * 256) { int k = i >> 8, c = i & 255; d_Wo2P[i] = (c < DD) ? Wo2[k * DD + c] : 0.f; return; }
    i -= DD * 256;
    if (i < 640) {
        d_bcat[i] = (i < DD) ? bk[i]
                  : (i < 2 * DD) ? bm[i - DD]
                  : (i < 3 * DD) ? bq[i - 2 * DD] * invs : 0.f;
        return;
    }
    i -= 640;
    if (i < DD * 256) { int k = i >> 8, c = i & 255; d_We2P[i] = (c < DD) ? We2[k * DD + c] : 0.f; return; }
    i -= DD * 256;
    if (i < 400 * 256) { int k = i >> 8, c = i & 255; d_Wa1P[i] = (c < DD) ? Wa1[k * DD + c] : 0.f; return; }
    i -= 400 * 256;
    if (i < DD * 256) { int k = i >> 8, c = i & 255; d_Wa2P[i] = (c < DD) ? Wa2[k * DD + c] : 0.f; return; }
    i -= DD * 256;
    if (i < DD * 256) { int k = i >> 8, c = i & 255; d_WattP[i] = (c < DD) ? Watt[k * DD + c] * qsc : 0.f; return; }
    i -= DD * 256;
    if (i < DD * 512) {
        int k = i >> 9, c = i & 511;
        d_WkmP[i] = (c < DD) ? Wk[(DD + k) * DD + c]
                  : (c < 2 * DD) ? Wm[(DD + k) * DD + (c - DD)] : 0.f;
    }
}

// ------------------------- f32x2 packed GEMM: 128x128 tile (exact fp32) -------------------------
__global__ __launch_bounds__(256, 2) void k_gemm2(
    int M, int Nreal, int K,
    const float* __restrict__ A, int lda,
    const float* __restrict__ B, int ldb,
    float* __restrict__ C, int ldc,
    const float* __restrict__ bias,
    const float* __restrict__ bnm, const float* __restrict__ bnr,
    const float* __restrict__ bng, const float* __restrict__ bnb) {
    __shared__ float As[8][128];
    __shared__ float Bs[8][128];
    int tid = threadIdx.x;
    int tx = tid % 16, ty = tid / 16;
    int row0 = blockIdx.y * 128, col0 = blockIdx.x * 128;
    unsigned long long acc[8][4];
#pragma unroll
    for (int i = 0; i < 8; i++)
#pragma unroll
        for (int j = 0; j < 4; j++) acc[i][j] = 0ULL;
    int rowA = row0 + (tid >> 1);
    int kA = (tid & 1) * 4;
    int rowB = tid >> 5;
    int colB = (tid & 31) * 4;
    for (int k0 = 0; k0 < K; k0 += 8) {
        float4 av = *(const float4*)&A[(size_t)rowA * lda + k0 + kA];
        if (bnm) {
            int g = k0 + kA;
            av.x = fmaxf((av.x - bnm[g])     * bnr[g]     * bng[g]     + bnb[g],     0.f);
            av.y = fmaxf((av.y - bnm[g + 1]) * bnr[g + 1] * bng[g + 1] + bnb[g + 1], 0.f);
            av.z = fmaxf((av.z - bnm[g + 2]) * bnr[g + 2] * bng[g + 2] + bnb[g + 2], 0.f);
            av.w = fmaxf((av.w - bnm[g + 3]) * bnr[g + 3] * bng[g + 3] + bnb[g + 3], 0.f);
        }
        int m = tid >> 1;
        As[kA + 0][m] = av.x; As[kA + 1][m] = av.y;
        As[kA + 2][m] = av.z; As[kA + 3][m] = av.w;
        *(float4*)&Bs[rowB][colB] = *(const float4*)&B[(size_t)(k0 + rowB) * ldb + col0 + colB];
        __syncthreads();
#pragma unroll
        for (int kk = 0; kk < 8; kk++) {
            float4 a0 = *(const float4*)&As[kk][ty * 8];
            float4 a1 = *(const float4*)&As[kk][ty * 8 + 4];
            ulonglong2 b01 = *(const ulonglong2*)&Bs[kk][tx * 8];
            ulonglong2 b23 = *(const ulonglong2*)&Bs[kk][tx * 8 + 4];
            unsigned long long bb[4] = { b01.x, b01.y, b23.x, b23.y };
            unsigned long long a2[8];
            PACK2(a2[0], a0.x, a0.x); PACK2(a2[1], a0.y, a0.y);
            PACK2(a2[2], a0.z, a0.z); PACK2(a2[3], a0.w, a0.w);
            PACK2(a2[4], a1.x, a1.x); PACK2(a2[5], a1.y, a1.y);
            PACK2(a2[6], a1.z, a1.z); PACK2(a2[7], a1.w, a1.w);
#pragma unroll
            for (int i = 0; i < 8; i++) {
                FMA2(acc[i][0], a2[i], bb[0]);
                FMA2(acc[i][1], a2[i], bb[1]);
                FMA2(acc[i][2], a2[i], bb[2]);
                FMA2(acc[i][3], a2[i], bb[3]);
            }
        }
        __syncthreads();
    }
#pragma unroll
    for (int i = 0; i < 8; i++) {
        int gm = row0 + ty * 8 + i;
        if (gm >= M) continue;
        float* crow = &C[(size_t)gm * ldc];
#pragma unroll
        for (int j = 0; j < 4; j++) {
            float lo, hi; UNPACK2(lo, hi, acc[i][j]);
            int c0 = col0 + tx * 8 + j * 2;
            if (c0 < Nreal)     crow[c0]     = lo + (bias ? bias[c0]     : 0.f);
            if (c0 + 1 < Nreal) crow[c0 + 1] = hi + (bias ? bias[c0 + 1] : 0.f);
        }
    }
}

// ------------------------- tf32 GEMM: 128x128 tile, 2-stage smem pipeline -------------------------
template<int DOSTAT>
__global__ __launch_bounds__(256, 2) void k_gemmT(
    int M, int Nreal, int K,
    const float* __restrict__ A, int lda,
    const float* __restrict__ B, int ldb,
    float* __restrict__ C, int ldc,
    const float* __restrict__ bias,
    const float* __restrict__ bnm, const float* __restrict__ bnr,
    const float* __restrict__ bng, const float* __restrict__ bnb) {
    __shared__ uint32_t As[2][8][132];
    __shared__ uint32_t Bs[2][8][132];
    __shared__ float cs[128], cs2[128];
    int tid = threadIdx.x;
    int lane = tid & 31, warp = tid >> 5;
    int wm = warp >> 2, wn = warp & 3;
    int gid = lane >> 2, tg = lane & 3;
    int row0 = blockIdx.y * 128, col0 = blockIdx.x * 128;
    if (DOSTAT && tid < 128) { cs[tid] = 0.f; cs2[tid] = 0.f; }

    float acc[4][4][4];
#pragma unroll
    for (int mt = 0; mt < 4; mt++)
#pragma unroll
        for (int nt = 0; nt < 4; nt++)
#pragma unroll
            for (int r = 0; r < 4; r++) acc[mt][nt][r] = 0.f;

    int rowA = row0 + (tid >> 1);
    int kA = (tid & 1) * 4;
    int rowB = tid >> 5;
    int colB = (tid & 31) * 4;
    int m0 = wm * 64, n0 = wn * 32;
    int mrow = tid >> 1;
    int nk = K / 8;

    float4 av, bv;
    {
        av = *(const float4*)&A[(size_t)rowA * lda + kA];
        if (bnm) {
            int g = kA;
            av.x = fmaxf((av.x - bnm[g])     * bnr[g]     * bng[g]     + bnb[g],     0.f);
            av.y = fmaxf((av.y - bnm[g + 1]) * bnr[g + 1] * bng[g + 1] + bnb[g + 1], 0.f);
            av.z = fmaxf((av.z - bnm[g + 2]) * bnr[g + 2] * bng[g + 2] + bnb[g + 2], 0.f);
            av.w = fmaxf((av.w - bnm[g + 3]) * bnr[g + 3] * bng[g + 3] + bnb[g + 3], 0.f);
        }
        bv = *(const float4*)&B[(size_t)rowB * ldb + col0 + colB];
        uint32_t u0, u1, u2, u3;
        CVT_TF32(u0, av.x); CVT_TF32(u1, av.y); CVT_TF32(u2, av.z); CVT_TF32(u3, av.w);
        As[0][kA + 0][mrow] = u0; As[0][kA + 1][mrow] = u1;
        As[0][kA + 2][mrow] = u2; As[0][kA + 3][mrow] = u3;
        CVT_TF32(u0, bv.x); CVT_TF32(u1, bv.y); CVT_TF32(u2, bv.z); CVT_TF32(u3, bv.w);
        Bs[0][rowB][colB] = u0; Bs[0][rowB][colB + 1] = u1;
        Bs[0][rowB][colB + 2] = u2; Bs[0][rowB][colB + 3] = u3;
    }

    for (int kt = 0; kt < nk; kt++) {
        int cur = kt & 1;
        int nxt = cur ^ 1;
        bool has = (kt + 1 < nk);
        if (has) {
            int k0 = (kt + 1) * 8;
            av = *(const float4*)&A[(size_t)rowA * lda + k0 + kA];
            if (bnm) {
                int g = k0 + kA;
                av.x = fmaxf((av.x - bnm[g])     * bnr[g]     * bng[g]     + bnb[g],     0.f);
                av.y = fmaxf((av.y - bnm[g + 1]) * bnr[g + 1] * bng[g + 1] + bnb[g + 1], 0.f);
                av.z = fmaxf((av.z - bnm[g + 2]) * bnr[g + 2] * bng[g + 2] + bnb[g + 2], 0.f);
                av.w = fmaxf((av.w - bnm[g + 3]) * bnr[g + 3] * bng[g + 3] + bnb[g + 3], 0.f);
            }
            bv = *(const float4*)&B[(size_t)(k0 + rowB) * ldb + col0 + colB];
        }
        __syncthreads();
        if (has) {
            uint32_t u0, u1, u2, u3;
            CVT_TF32(u0, av.x); CVT_TF32(u1, av.y); CVT_TF32(u2, av.z); CVT_TF32(u3, av.w);
            As[nxt][kA + 0][mrow] = u0; As[nxt][kA + 1][mrow] = u1;
            As[nxt][kA + 2][mrow] = u2; As[nxt][kA + 3][mrow] = u3;
            CVT_TF32(u0, bv.x); CVT_TF32(u1, bv.y); CVT_TF32(u2, bv.z); CVT_TF32(u3, bv.w);
            Bs[nxt][rowB][colB] = u0; Bs[nxt][rowB][colB + 1] = u1;
            Bs[nxt][rowB][colB + 2] = u2; Bs[nxt][rowB][colB + 3] = u3;
        }
        uint32_t af[4][4], bf[4][2];
#pragma unroll
        for (int mt = 0; mt < 4; mt++) {
            int mb = m0 + mt * 16 + gid;
            af[mt][0] = As[cur][tg][mb];
            af[mt][1] = As[cur][tg][mb + 8];
            af[mt][2] = As[cur][tg + 4][mb];
            af[mt][3] = As[cur][tg + 4][mb + 8];
        }
#pragma unroll
        for (int nt = 0; nt < 4; nt++) {
            int nb = n0 + nt * 8 + gid;
            bf[nt][0] = Bs[cur][tg][nb];
            bf[nt][1] = Bs[cur][tg + 4][nb];
        }
#pragma unroll
        for (int mt = 0; mt < 4; mt++)
#pragma unroll
            for (int nt = 0; nt < 4; nt++)
                MMA_TF32(acc[mt][nt][0], acc[mt][nt][1], acc[mt][nt][2], acc[mt][nt][3],
                         af[mt][0], af[mt][1], af[mt][2], af[mt][3],
                         bf[nt][0], bf[nt][1]);
    }

    float colS[4][2], colS2[4][2];
#pragma unroll
    for (int nt = 0; nt < 4; nt++) { colS[nt][0] = colS[nt][1] = 0.f; colS2[nt][0] = colS2[nt][1] = 0.f; }
#pragma unroll
    for (int mt = 0; mt < 4; mt++) {
        int r = row0 + m0 + mt * 16 + gid;
#pragma unroll
        for (int nt = 0; nt < 4; nt++) {
            int c = col0 + n0 + nt * 8 + tg * 2;
            float b0 = (bias && c < Nreal)     ? bias[c]     : 0.f;
            float b1 = (bias && c + 1 < Nreal) ? bias[c + 1] : 0.f;
            float v0 = acc[mt][nt][0] + b0;
            float v1 = acc[mt][nt][1] + b1;
            float v2 = acc[mt][nt][2] + b0;
            float v3 = acc[mt][nt][3] + b1;
            float* cr0 = &C[(size_t)r * ldc];
            float* cr1 = &C[(size_t)(r + 8) * ldc];
            if (c < Nreal)     { cr0[c] = v0; cr1[c] = v2; }
            if (c + 1 < Nreal) { cr0[c + 1] = v1; cr1[c + 1] = v3; }
            if (DOSTAT) {
                colS[nt][0]  += v0 + v2;
                colS2[nt][0] += v0 * v0 + v2 * v2;
                colS[nt][1]  += v1 + v3;
                colS2[nt][1] += v1 * v1 + v3 * v3;
            }
        }
    }
    if (DOSTAT) {
#pragma unroll
        for (int nt = 0; nt < 4; nt++) {
#pragma unroll
            for (int p = 0; p < 2; p++) {
                float a = colS[nt][p], b = colS2[nt][p];
                for (int o = 16; o >= 4; o >>= 1) {
                    a += __shfl_down_sync(0xffffffffu, a, o);
                    b += __shfl_down_sync(0xffffffffu, b, o);
                }
                colS[nt][p] = a; colS2[nt][p] = b;
            }
        }
        __syncthreads();
        if (gid == 0) {
#pragma unroll
            for (int nt = 0; nt < 4; nt++) {
                int lc = n0 + nt * 8 + tg * 2;
                atomicAdd(&cs[lc],      colS[nt][0]);
                atomicAdd(&cs2[lc],     colS2[nt][0]);
                atomicAdd(&cs[lc + 1],  colS[nt][1]);
                atomicAdd(&cs2[lc + 1], colS2[nt][1]);
            }
        }
        __syncthreads();
        if (tid < 128) {
            int gc = col0 + tid;
            if (gc < Nreal) {
                atomicAdd(&d_colsum[gc],  cs[tid]);
                atomicAdd(&d_colsum2[gc], cs2[tid]);
            }
        }
    }
}

// ------------------------- edge attention by src-CSR: one warp per src node -------------------------
__global__ __launch_bounds__(256) void k_D1s(const int* __restrict__ ei,
                                             const int* __restrict__ ntp) {
    int gw = (blockIdx.x * blockDim.x + threadIdx.x) >> 5;
    int lane = threadIdx.x & 31;
    int w = threadIdx.x >> 5;
    __shared__ float sq[8][DD];
    if (gw >= NN) return;
    int n = gw;
    const float* qrow = &d_XKMQ[(size_t)n * 600 + 400];
    for (int c = lane; c < DD; c += 32) sq[w][c] = qrow[c];
    __syncwarp();
    int h = lane >> 3, r = lane & 7;
    float denacc = 0.f;
    int beg = d_srcOff[n], end = d_srcOff[n + 1];
    for (int e = beg; e < end; e++) {
        int i = d_csrS[e];
        int dd, kidx;
        if (i < EE) { dd = ei[EE + i]; kidx = i >> 10; }
        else { dd = n; kidx = BB + ntp[n]; }
        const float* krow = &d_XKMQ[(size_t)dd * 600];
        const float* kadd = &d_UKM[kidx * 400];
        float p = 0.f;
#pragma unroll
        for (int j = 0; j < 4; j++) {
            int idx = r + 8 * j;
            if (idx < 25) {
                int d0 = h * 50 + idx * 2;
                float2 k2 = *(const float2*)(krow + d0);
                float2 a2 = *(const float2*)(kadd + d0);
                p += sq[w][d0] * (k2.x + a2.x) + sq[w][d0 + 1] * (k2.y + a2.y);
            }
        }
        p += __shfl_down_sync(0xffffffffu, p, 4);
        p += __shfl_down_sync(0xffffffffu, p, 2);
        p += __shfl_down_sync(0xffffffffu, p, 1);
        if (r == 0) {
            float exv = __expf(p);
            d_ex[(size_t)i * 4 + h] = exv;
            denacc += exv;
        }
    }
    if (r == 0) d_den[n * 4 + h] = denacc;
}

// ------------------------- aggregation: one warp per dst node -------------------------
__global__ __launch_bounds__(256) void k_D2w(const int* __restrict__ ei,
                                             const int* __restrict__ ntp) {
    int gw = (blockIdx.x * blockDim.x + threadIdx.x) >> 5;
    int lane = threadIdx.x & 31;
    int w = threadIdx.x >> 5;
    if (gw >= NN) return;
    int n = gw;
    int beg = d_dstOff[n], end = d_dstOff[n + 1];
    __shared__ float s_al[8][16][4];
    __shared__ int s_j[8][16], s_u[8][16];
    float acc[7];
#pragma unroll
    for (int k = 0; k < 7; k++) acc[k] = 0.f;
    for (int base = beg; base < end; base += 16) {
        int cnt = min(16, end - base);
        if (lane < cnt) {
            int i = d_csr[base + lane];
            int s, j, u;
            if (i < EE) { s = ei[i]; j = s; u = i >> 10; }
            else { int nn2 = i - EE; s = nn2; j = nn2; u = BB + ntp[nn2]; }
            s_j[w][lane] = j;
            s_u[w][lane] = u;
            float csf = (float)d_cntSrc[s];
#pragma unroll
            for (int hh = 0; hh < 4; hh++)
                s_al[w][lane][hh] = __fdividef(d_ex[(size_t)i * 4 + hh], d_den[s * 4 + hh]) * csf;
        }
        __syncwarp();
        for (int r = 0; r < cnt; r++) {
            const float* mrow = &d_XKMQ[(size_t)s_j[w][r] * 600 + 200];
            const float* urow = &d_UKM[s_u[w][r] * 400 + 200];
            float a0 = s_al[w][r][0], a1 = s_al[w][r][1];
            float a2 = s_al[w][r][2], a3 = s_al[w][r][3];
#pragma unroll
            for (int k = 0; k < 7; k++) {
                int c = lane + 32 * k;
                if (c < DD) {
                    float al = c < 50 ? a0 : c < 100 ? a1 : c < 150 ? a2 : a3;
                    acc[k] += al * (mrow[c] + urow[c]);
                }
            }
        }
        __syncwarp();
    }
#pragma unroll
    for (int k = 0; k < 7; k++) {
        int c = lane + 32 * k;
        if (c < DD) d_aggr[(size_t)n * DD + c] = acc[k];
    }
}

__global__ void k_stat3() {
    int d = threadIdx.x;
    if (d >= DD) return;
    float m = d_colsum[d] / (float)NN;
    float var = d_colsum2[d] / (float)NN - m * m;
    d_bn3m[d] = m;
    d_bn3r[d] = rsqrtf(var + 1e-5f);
}

// ------------------------- launch -------------------------
extern "C" void kernel_launch(void* const* d_in, const int* in_sizes, int n_in,
                              void* d_out, int out_size) {
    const float* x    = (const float*)d_in[0];
    const float* sent = (const float*)d_in[2];
    const float* We1  = (const float*)d_in[3];
    const float* be1  = (const float*)d_in[4];
    const float* ge1  = (const float*)d_in[5];
    const float* bte1 = (const float*)d_in[6];
    const float* We2  = (const float*)d_in[7];
    const float* be2  = (const float*)d_in[8];
    const float* Wa1  = (const float*)d_in[9];
    const float* ba1  = (const float*)d_in[10];
    const float* ga1  = (const float*)d_in[11];
    const float* bta1 = (const float*)d_in[12];
    const float* Wa2  = (const float*)d_in[13];
    const float* ba2  = (const float*)d_in[14];
    const float* Watt = (const float*)d_in[15];
    const float* Wk   = (const float*)d_in[16];
    const float* bk   = (const float*)d_in[17];
    const float* Wm   = (const float*)d_in[18];
    const float* bm   = (const float*)d_in[19];
    const float* Wq   = (const float*)d_in[20];
    const float* bq   = (const float*)d_in[21];
    const float* Wo1  = (const float*)d_in[22];
    const float* bo1  = (const float*)d_in[23];
    const float* go1  = (const float*)d_in[24];
    const float* bto1 = (const float*)d_in[25];
    const float* Wo2  = (const float*)d_in[26];
    const float* bo2  = (const float*)d_in[27];
    const int* ei     = (const int*)d_in[28];
    const int* et     = (const int*)d_in[29];
    const int* ntp    = (const int*)d_in[30];
    float* out = (float*)d_out;

    void* tmp;
    cudaGetSymbolAddress(&tmp, d_Wcat);   float* pWcat  = (float*)tmp;
    cudaGetSymbolAddress(&tmp, d_bcat);   float* pbcat  = (float*)tmp;
    cudaGetSymbolAddress(&tmp, d_Wo1P);   float* pWo1P  = (float*)tmp;
    cudaGetSymbolAddress(&tmp, d_Wo2P);   float* pWo2P  = (float*)tmp;
    cudaGetSymbolAddress(&tmp, d_We2P);   float* pWe2P  = (float*)tmp;
    cudaGetSymbolAddress(&tmp, d_Wa1P);   float* pWa1P  = (float*)tmp;
    cudaGetSymbolAddress(&tmp, d_Wa2P);   float* pWa2P  = (float*)tmp;
    cudaGetSymbolAddress(&tmp, d_WattP);  float* pWattP = (float*)tmp;
    cudaGetSymbolAddress(&tmp, d_WkmP);   float* pWkmP  = (float*)tmp;
    cudaGetSymbolAddress(&tmp, d_preAll); float* pPre   = (float*)tmp;
    cudaGetSymbolAddress(&tmp, d_embAll); float* pEmb   = (float*)tmp;
    cudaGetSymbolAddress(&tmp, d_A2);     float* pA2    = (float*)tmp;
    cudaGetSymbolAddress(&tmp, d_h2All);  float* pH2    = (float*)tmp;
    cudaGetSymbolAddress(&tmp, d_RtabP);  float* pRtab  = (float*)tmp;
    cudaGetSymbolAddress(&tmp, d_RtabT);  float* pRtabT = (float*)tmp;
    cudaGetSymbolAddress(&tmp, d_qmat);   float* pQ     = (float*)tmp;
    cudaGetSymbolAddress(&tmp, d_P);      float* pP     = (float*)tmp;
    cudaGetSymbolAddress(&tmp, d_Wt);     float* pWt    = (float*)tmp;
    cudaGetSymbolAddress(&tmp, d_S);      float* pS     = (float*)tmp;
    cudaGetSymbolAddress(&tmp, d_UKM);    float* pUKM   = (float*)tmp;
    cudaGetSymbolAddress(&tmp, d_XKMQ);   float* pXKMQ  = (float*)tmp;
    cudaGetSymbolAddress(&tmp, d_aggr);   float* pAggr  = (float*)tmp;
    cudaGetSymbolAddress(&tmp, d_Y1);     float* pY1    = (float*)tmp;
    cudaGetSymbolAddress(&tmp, d_bn1m);   float* pb1m   = (float*)tmp;
    cudaGetSymbolAddress(&tmp, d_bn1r);   float* pb1r   = (float*)tmp;
    cudaGetSymbolAddress(&tmp, d_bn2m);   float* pb2m   = (float*)tmp;
    cudaGetSymbolAddress(&tmp, d_bn2r);   float* pb2r   = (float*)tmp;
    cudaGetSymbolAddress(&tmp, d_bn3m);   float* pb3m   = (float*)tmp;
    cudaGetSymbolAddress(&tmp, d_bn3r);   float* pb3r   = (float*)tmp;

    k_zero<<<1024, 256>>>(ntp);
    k_edgehist<<<EE / 256, 256>>>(ei, et, ntp);
    {
        int total = DD * 640 + 2 * DD * 256 + 640 + DD * 256 + 400 * 256 + DD * 256 + DD * 256 + DD * 512;
        k_pack<<<(total + 255) / 256, 256>>>(Wk, Wm, Wq, bk, bm, bq, Wo1, Wo2, We2, Wa1, Wa2, Watt);
    }
    k_scanA2<<<dim3(50, 2), 1024>>>();
    k_scanB2<<<2, 64>>>();
    k_scanC2<<<dim3(50, 2), 1024>>>();
    k_csrfill<<<(TOTROWS + 255) / 256, 256>>>(ei);
    k_segsum3<<<400, 128>>>(x);
    k_meanT<<<(NT1 * DD + 255) / 256, 256>>>();
    k_tables<<<NCOMBO + NTY, 256>>>(We1, be1);
    k_bnstat1p<<<DD, 128>>>();
    // embAll = relu(bn1(preAll)) @ We2 + be2   (612 x 200 x 200, fp32)
    k_gemm2<<<dim3(2, 5), 256>>>(612, DD, DD, pPre, DD, pWe2P, 256, pEmb, DD,
                                 be2, pb1m, pb1r, ge1, bte1);
    k_buildA2<<<NCOMBO, 512>>>();
    // h2All = [embE | meanT] @ Wa1 + ba1   (608 x 200 x 400)
    k_gemm2<<<dim3(2, 5), 256>>>(NCOMBO, DD, 400, pA2, 400, pWa1P, 256, pH2, DD,
                                 ba1, nullptr, nullptr, nullptr, nullptr);
    k_bnstat2p<<<DD, 128>>>();
    // RtabP = relu(bn2(h2All)) @ Wa2 + ba2   (608 x 200 x 200, ldc=256)
    k_gemm2<<<dim3(2, 5), 256>>>(NCOMBO, DD, DD, pH2, DD, pWa2P, 256, pRtab, 256,
                                 ba2, pb2m, pb2r, ga1, bta1);
    // qmat = sent @ (Watt * 1/sqrt(200))   (256 x 200 x 200)
    k_gemm2<<<dim3(2, 2), 256>>>(BB, DD, DD, sent, DD, pWattP, 256, pQ, DD,
                                 nullptr, nullptr, nullptr, nullptr, nullptr);
    k_transT<<<(DD * 640 + NTY * DD + 255) / 256, 256>>>();
    // P = qmat @ RtabT   (256 x 608 x 200, ldc=640)
    k_gemm2<<<dim3(5, 2), 256>>>(BB, NCOMBO, DD, pQ, DD, pRtabT, 640, pP, 640,
                                 nullptr, nullptr, nullptr, nullptr, nullptr);
    k_attnP<<<BB, 256>>>();
    // upd = Wt @ RtabP   (256 x 200 x 640) -> d_S rows 0..255
    k_gemm2<<<dim3(2, 2), 256>>>(BB, DD, 640, pWt, 640, pRtab, 256, pS, DD,
                                 nullptr, nullptr, nullptr, nullptr, nullptr);
    // UKM = S @ [Wk2|Wm2]   (260 x 400 x 200)
    k_gemm2<<<dim3(4, 3), 256>>>(BB + NTY, 400, DD, pS, DD, pWkmP, 512, pUKM, 400,
                                 nullptr, nullptr, nullptr, nullptr, nullptr);
    {   // XKMQ = x @ [Wk1|Wm1|Wq*invs] + [bk|bm|bq*invs]  (tensor cores)
        dim3 g(5, NN / 128);
        k_gemmT<0><<<g, 256>>>(NN, 600, DD, x, DD, pWcat, 640, pXKMQ, 600,
                               pbcat, nullptr, nullptr, nullptr, nullptr);
    }
    k_D1s<<<NN / 8, 256>>>(ei, ntp);
    k_D2w<<<NN / 8, 256>>>(ei, ntp);
    {   // Y1 = aggr @ Wo1 + bo1  (+ fused column stats)
        dim3 g(2, NN / 128);
        k_gemmT<1><<<g, 256>>>(NN, DD, DD, pAggr, DD, pWo1P, 256, pY1, DD,
                               bo1, nullptr, nullptr, nullptr, nullptr);
    }
    k_stat3<<<1, 256>>>();
    {   // out = relu(bn3(Y1)) @ Wo2 + bo2
        dim3 g(2, NN / 128);
        k_gemmT<0><<<g, 256>>>(NN, DD, DD, pY1, DD, pWo2P, 256, out, DD,
                               bo2, pb3m, pb3r, go1, bto1);
    }
}

// round 8
// speedup vs baseline: 1.2194x; 1.2194x over previous
#include <cuda_runtime.h>
#include <math.h>
#include <stdint.h>

#define DD 200
#define NTY 4
#define NET 38
#define NT1 39
#define BB 256
#define LL 1024
#define EE 262144
#define NN 51200
#define NCOMBO 608
#define TOTROWS (EE + NN)

// f32x2 packed-math helpers
#define FMA2(d,a,b)  asm("fma.rn.f32x2 %0, %1, %2, %3;" : "=l"(d) : "l"(a), "l"(b), "l"(d))
#define PACK2(d,x,y) asm("mov.b64 %0, {%1, %2};" : "=l"(d) : "f"(x), "f"(y))
#define UNPACK2(x,y,d) asm("mov.b64 {%0, %1}, %2;" : "=f"(x), "=f"(y) : "l"(d))

#define CVT_TF32(u,f) asm("cvt.rna.tf32.f32 %0, %1;" : "=r"(u) : "f"(f))
#define MMA_TF32(c0,c1,c2,c3,a0,a1,a2,a3,b0,b1) \
  asm("mma.sync.aligned.m16n8k8.row.col.f32.tf32.tf32.f32 " \
      "{%0,%1,%2,%3},{%4,%5,%6,%7},{%8,%9},{%0,%1,%2,%3};" \
      : "+f"(c0),"+f"(c1),"+f"(c2),"+f"(c3) \
      : "r"(a0),"r"(a1),"r"(a2),"r"(a3),"r"(b0),"r"(b1))

// ------------------------- scratch -------------------------
__device__ float d_coeff[(size_t)NN * NT1];
__device__ float d_sums[NT1 * DD];
__device__ int   d_cntT[NT1];
__device__ int   d_cntE[NCOMBO];
__device__ int   d_cntN[NTY];
__device__ int   d_combo[EE];
__device__ int   d_cntSrc[NN];
__device__ int   d_dstCnt[NN];
__device__ int   d_dstOff[NN + 1];
__device__ int   d_cursor[NN];
__device__ int   d_csr[TOTROWS];
__device__ int   d_blkSum[50];
__device__ float d_meanT[NT1 * DD];
__device__ float d_preE[NCOMBO * DD];
__device__ float d_preS[NTY * DD];
__device__ float d_embE[NCOMBO * DD];
__device__ float d_embS[NTY * DD];
__device__ float d_h2[NCOMBO * DD];
__device__ float d_Rtab[NCOMBO * DD];
__device__ float d_bn1m[DD], d_bn1r[DD], d_bn2m[DD], d_bn2r[DD], d_bn3m[DD], d_bn3r[DD];
__device__ float d_upd[BB * DD];
__device__ float d_UKall[(BB + NTY) * DD];
__device__ float d_UMall[(BB + NTY) * DD];
__device__ float d_Wcat[DD * 640];
__device__ float d_bcat[640];
__device__ float d_Wo1P[DD * 256];
__device__ float d_Wo2P[DD * 256];
__device__ float d_XKMQ[(size_t)NN * 600];    // per-node [XK+bk | XM+bm | (XQ+bq)*invs]
__device__ float d_ex[(size_t)TOTROWS * 4];
__device__ float d_den[NN * 4];
__device__ float d_aggr[(size_t)NN * DD];
__device__ float d_Y1[(size_t)NN * DD];
__device__ float d_colsum[DD], d_colsum2[DD];

// ------------------------- zero init + node hist (fused) -------------------------
__global__ void k_zero(const int* __restrict__ ntp) {
    long long i0 = (long long)blockIdx.x * blockDim.x + threadIdx.x;
    long long st = (long long)gridDim.x * blockDim.x;
    for (long long i = i0; i < (long long)NT1 * NN; i += st) d_coeff[i] = 0.f;
    for (long long i = i0; i < (long long)NN * 4; i += st) d_den[i] = 0.f;
    for (long long i = i0; i < NT1 * DD; i += st) d_sums[i] = 0.f;
    for (long long i = i0; i < NCOMBO; i += st) d_cntE[i] = 0;
    for (long long i = i0; i < NT1; i += st) d_cntT[i] = 0;
    for (long long i = i0; i < NTY; i += st) d_cntN[i] = 0;
    for (long long i = i0; i < DD; i += st) { d_colsum[i] = 0.f; d_colsum2[i] = 0.f; }
    for (long long i = i0; i < NN; i += st) {
        d_cntSrc[i] = 1;
        d_dstCnt[i] = 1;
        atomicAdd(&d_cntN[ntp[i]], 1);
    }
}

__global__ void k_edgehist(const int* __restrict__ ei, const int* __restrict__ et,
                           const int* __restrict__ ntp) {
    int e = blockIdx.x * blockDim.x + threadIdx.x;
    if (e >= EE) return;
    int s  = ei[e];
    int dd = ei[EE + e];
    int t  = et[e];
    atomicAdd(&d_coeff[(size_t)dd * NT1 + t],  1.f);
    atomicAdd(&d_coeff[(size_t)s  * NT1 + t], -1.f);
    atomicAdd(&d_cntT[t], 1);
    int c = (t << 4) | (ntp[s] << 2) | ntp[dd];
    d_combo[e] = c;
    atomicAdd(&d_cntE[c], 1);
    atomicAdd(&d_cntSrc[s], 1);
    atomicAdd(&d_dstCnt[dd], 1);
}

// ------------------------- dst-CSR build (3-phase parallel scan) -------------------------
__global__ void k_scanA() {
    __shared__ int sm[1024];
    int tid = threadIdx.x;
    sm[tid] = d_dstCnt[blockIdx.x * 1024 + tid];
    __syncthreads();
    for (int o = 512; o > 0; o >>= 1) {
        if (tid < o) sm[tid] += sm[tid + o];
        __syncthreads();
    }
    if (tid == 0) d_blkSum[blockIdx.x] = sm[0];
}

__global__ void k_scanB() {
    __shared__ int sm[64];
    int tid = threadIdx.x;
    int v = (tid < 50) ? d_blkSum[tid] : 0;
    sm[tid] = v;
    __syncthreads();
    for (int o = 1; o < 64; o <<= 1) {
        int t = (tid >= o) ? sm[tid - o] : 0;
        __syncthreads();
        sm[tid] += t;
        __syncthreads();
    }
    if (tid < 50) d_blkSum[tid] = sm[tid] - v;
    if (tid == 49) d_dstOff[NN] = sm[49];
}

__global__ void k_scanC() {
    __shared__ int sm[1024];
    int tid = threadIdx.x;
    int g = blockIdx.x * 1024 + tid;
    int v = d_dstCnt[g];
    sm[tid] = v;
    __syncthreads();
    for (int o = 1; o < 1024; o <<= 1) {
        int t = (tid >= o) ? sm[tid - o] : 0;
        __syncthreads();
        sm[tid] += t;
        __syncthreads();
    }
    int excl = sm[tid] - v + d_blkSum[blockIdx.x];
    d_dstOff[g] = excl;
    d_cursor[g] = excl;
}

__global__ void k_csrfill(const int* __restrict__ ei) {
    int i = blockIdx.x * blockDim.x + threadIdx.x;
    if (i >= TOTROWS) return;
    int dst = (i < EE) ? ei[EE + i] : (i - EE);
    int pos = atomicAdd(&d_cursor[dst], 1);
    d_csr[pos] = i;
}

// ------------------------- segment sums -------------------------
__global__ __launch_bounds__(128) void k_segsum3(const float* __restrict__ x) {
    __shared__ unsigned long long cf2[128][NT1];
    int tid = threadIdx.x;
    int n0 = blockIdx.x * 128;
    for (int i = tid; i < 128 * NT1; i += 128) {
        float c = d_coeff[(size_t)(n0 + i / NT1) * NT1 + (i % NT1)];
        unsigned long long c2; PACK2(c2, c, c);
        cf2[i / NT1][i % NT1] = c2;
    }
    __syncthreads();
    if (tid < 100) {
        unsigned long long acc[NT1];
#pragma unroll
        for (int t = 0; t < NT1; t++) acc[t] = 0ULL;
        for (int nn = 0; nn < 128; nn++) {
            float2 xv = *(const float2*)&x[(size_t)(n0 + nn) * DD + tid * 2];
            unsigned long long xv2; PACK2(xv2, xv.x, xv.y);
#pragma unroll
            for (int t = 0; t < NT1; t++)
                FMA2(acc[t], cf2[nn][t], xv2);
        }
#pragma unroll
        for (int t = 0; t < NT1; t++) {
            float lo, hi; UNPACK2(lo, hi, acc[t]);
            if (lo != 0.f) atomicAdd(&d_sums[t * DD + tid * 2], lo);
            if (hi != 0.f) atomicAdd(&d_sums[t * DD + tid * 2 + 1], hi);
        }
    }
}

__global__ void k_meanT() {
    int i = blockIdx.x * blockDim.x + threadIdx.x;
    if (i >= NT1 * DD) return;
    int t = i / DD;
    float c = (float)d_cntT[t];
    if (c < 1.f) c = 1.f;
    d_meanT[i] = d_sums[i] / c;
}

// ------------------------- combo tables -------------------------
__global__ void k_tables(const float* __restrict__ We1, const float* __restrict__ be1) {
    int c = blockIdx.x, d = threadIdx.x;
    if (d >= DD) return;
    if (c < NCOMBO) {
        int t = c >> 4, a = (c >> 2) & 3, b = c & 3;
        d_preE[c * DD + d] = We1[t * DD + d] + We1[(NT1 + a) * DD + d]
                           + We1[(NT1 + NTY + b) * DD + d] + be1[d];
    } else {
        int t = c - NCOMBO;
        d_preS[t * DD + d] = We1[NET * DD + d] + We1[(NT1 + t) * DD + d]
                           + We1[(NT1 + NTY + t) * DD + d] + be1[d];
    }
}

__global__ void k_bnstat1p() {
    int d = blockIdx.x, tid = threadIdx.x;
    __shared__ double rs[128], rs2[128];
    double s = 0.0, s2 = 0.0;
    for (int c = tid; c < NCOMBO; c += 128) {
        double w = (double)d_cntE[c], v = (double)d_preE[c * DD + d];
        s += w * v; s2 += w * v * v;
    }
    if (tid < NTY) {
        double w = (double)d_cntN[tid], v = (double)d_preS[tid * DD + d];
        s += w * v; s2 += w * v * v;
    }
    rs[tid] = s; rs2[tid] = s2;
    __syncthreads();
    for (int o = 64; o > 0; o >>= 1) {
        if (tid < o) { rs[tid] += rs[tid + o]; rs2[tid] += rs2[tid + o]; }
        __syncthreads();
    }
    if (tid == 0) {
        double m = rs[0] / (double)TOTROWS;
        double var = rs2[0] / (double)TOTROWS - m * m;
        d_bn1m[d] = (float)m;
        d_bn1r[d] = rsqrtf((float)var + 1e-5f);
    }
}

// 2 rows per block: halves We2 re-read traffic.
__global__ void k_emb(const float* __restrict__ We2, const float* __restrict__ be2,
                      const float* __restrict__ g, const float* __restrict__ bt) {
    int c0 = blockIdx.x * 2, c1 = c0 + 1;
    int d = threadIdx.x;
    __shared__ float a0[DD], a1[DD];
    const float* r0 = (c0 < NCOMBO) ? &d_preE[c0 * DD] : &d_preS[(c0 - NCOMBO) * DD];
    const float* r1 = (c1 < NCOMBO) ? &d_preE[c1 * DD] : &d_preS[(c1 - NCOMBO) * DD];
    if (d < DD) {
        float bn = d_bn1m[d], br = d_bn1r[d], gg = g[d], bb = bt[d];
        a0[d] = fmaxf((r0[d] - bn) * br * gg + bb, 0.f);
        a1[d] = fmaxf((r1[d] - bn) * br * gg + bb, 0.f);
    }
    __syncthreads();
    if (d < DD) {
        float x0 = 0.f, x1 = 0.f;
        for (int k = 0; k < DD; k++) {
            float w = We2[k * DD + d];
            x0 += a0[k] * w;
            x1 += a1[k] * w;
        }
        float bb = be2[d];
        float* dst0 = (c0 < NCOMBO) ? &d_embE[c0 * DD] : &d_embS[(c0 - NCOMBO) * DD];
        float* dst1 = (c1 < NCOMBO) ? &d_embE[c1 * DD] : &d_embS[(c1 - NCOMBO) * DD];
        dst0[d] = x0 + bb;
        dst1[d] = x1 + bb;
    }
}

// 2 combos per block; combos 2c/2c+1 share etype => shared meanT term.
__global__ void k_h2pre(const float* __restrict__ Wa1, const float* __restrict__ ba1) {
    int c0 = blockIdx.x * 2, c1 = c0 + 1;
    int d = threadIdx.x;
    __shared__ float e0[DD], e1[DD], mt[DD];
    int t = c0 >> 4;
    if (d < DD) {
        e0[d] = d_embE[c0 * DD + d];
        e1[d] = d_embE[c1 * DD + d];
        mt[d] = d_meanT[t * DD + d];
    }
    __syncthreads();
    if (d < DD) {
        float am = 0.f;
        for (int k = 0; k < DD; k++) am += mt[k] * Wa1[(DD + k) * DD + d];
        float acc0 = ba1[d] + am, acc1 = acc0;
        for (int k = 0; k < DD; k++) {
            float w = Wa1[k * DD + d];
            acc0 += e0[k] * w;
            acc1 += e1[k] * w;
        }
        d_h2[c0 * DD + d] = acc0;
        d_h2[c1 * DD + d] = acc1;
    }
}

__global__ void k_bnstat2p() {
    int d = blockIdx.x, tid = threadIdx.x;
    __shared__ double rs[128], rs2[128];
    double s = 0.0, s2 = 0.0;
    for (int c = tid; c < NCOMBO; c += 128) {
        double w = (double)d_cntE[c], v = (double)d_h2[c * DD + d];
        s += w * v; s2 += w * v * v;
    }
    rs[tid] = s; rs2[tid] = s2;
    __syncthreads();
    for (int o = 64; o > 0; o >>= 1) {
        if (tid < o) { rs[tid] += rs[tid + o]; rs2[tid] += rs2[tid + o]; }
        __syncthreads();
    }
    if (tid == 0) {
        double m = rs[0] / (double)EE;
        double var = rs2[0] / (double)EE - m * m;
        d_bn2m[d] = (float)m;
        d_bn2r[d] = rsqrtf((float)var + 1e-5f);
    }
}

// 2 combos per block.
__global__ void k_Rtab(const float* __restrict__ Wa2, const float* __restrict__ ba2,
                       const float* __restrict__ g, const float* __restrict__ bt) {
    int c0 = blockIdx.x * 2, c1 = c0 + 1;
    int d = threadIdx.x;
    __shared__ float a0[DD], a1[DD];
    if (d < DD) {
        float bn = d_bn2m[d], br = d_bn2r[d], gg = g[d], bb = bt[d];
        a0[d] = fmaxf((d_h2[c0 * DD + d] - bn) * br * gg + bb, 0.f);
        a1[d] = fmaxf((d_h2[c1 * DD + d] - bn) * br * gg + bb, 0.f);
    }
    __syncthreads();
    if (d < DD) {
        float x0 = 0.f, x1 = 0.f;
        for (int k = 0; k < DD; k++) {
            float w = Wa2[k * DD + d];
            x0 += a0[k] * w;
            x1 += a1[k] * w;
        }
        float bb = ba2[d];
        d_Rtab[c0 * DD + d] = x0 + bb;
        d_Rtab[c1 * DD + d] = x1 + bb;
    }
}

// ------------------------- fused graph attention: 2 graphs per block -------------------------
__global__ __launch_bounds__(256) void k_attn(const float* __restrict__ sent,
                                              const float* __restrict__ Watt) {
    int b0 = blockIdx.x * 2, b1 = b0 + 1;
    int tid = threadIdx.x;
    __shared__ float sv0[DD], sv1[DD], q0[DD], q1[DD];
    __shared__ float Pb0[NCOMBO], Pb1[NCOMBO], Wa0[NCOMBO], Wa1s[NCOMBO];
    __shared__ float red[256];
    if (tid < DD) { sv0[tid] = sent[b0 * DD + tid]; sv1[tid] = sent[b1 * DD + tid]; }
    for (int i = tid; i < NCOMBO; i += 256) { Wa0[i] = 0.f; Wa1s[i] = 0.f; }
    __syncthreads();
    if (tid < DD) {
        float a0 = 0.f, a1 = 0.f;
        for (int k = 0; k < DD; k++) {
            float w = Watt[k * DD + tid];
            a0 += sv0[k] * w;
            a1 += sv1[k] * w;
        }
        q0[tid] = a0 * 0.07071067811865475f;
        q1[tid] = a1 * 0.07071067811865475f;
    }
    __syncthreads();
    int lane = tid & 31, w = tid >> 5;
    for (int c = w; c < NCOMBO; c += 8) {
        float p0 = 0.f, p1 = 0.f;
        for (int k = lane; k < DD; k += 32) {
            float r = d_Rtab[c * DD + k];
            p0 += q0[k] * r;
            p1 += q1[k] * r;
        }
        for (int o = 16; o > 0; o >>= 1) {
            p0 += __shfl_down_sync(0xffffffffu, p0, o);
            p1 += __shfl_down_sync(0xffffffffu, p1, o);
        }
        if (lane == 0) { Pb0[c] = p0; Pb1[c] = p1; }
    }
    __syncthreads();
    // softmax + combo-mass for graph b0
    {
        int cid[4]; float sc[4]; float lmax = -1e30f;
#pragma unroll
        for (int j = 0; j < 4; j++) {
            int e = b0 * LL + tid + j * 256;
            cid[j] = d_combo[e];
            sc[j] = Pb0[cid[j]];
            lmax = fmaxf(lmax, sc[j]);
        }
        red[tid] = lmax; __syncthreads();
        for (int s = 128; s > 0; s >>= 1) { if (tid < s) red[tid] = fmaxf(red[tid], red[tid + s]); __syncthreads(); }
        float bmax = red[0]; __syncthreads();
        float lsum = 0.f;
#pragma unroll
        for (int j = 0; j < 4; j++) { sc[j] = expf(sc[j] - bmax); lsum += sc[j]; }
        red[tid] = lsum; __syncthreads();
        for (int s = 128; s > 0; s >>= 1) { if (tid < s) red[tid] += red[tid + s]; __syncthreads(); }
        float inv = 1.f / red[0]; __syncthreads();
#pragma unroll
        for (int j = 0; j < 4; j++) atomicAdd(&Wa0[cid[j]], sc[j] * inv);
    }
    __syncthreads();
    // softmax + combo-mass for graph b1
    {
        int cid[4]; float sc[4]; float lmax = -1e30f;
#pragma unroll
        for (int j = 0; j < 4; j++) {
            int e = b1 * LL + tid + j * 256;
            cid[j] = d_combo[e];
            sc[j] = Pb1[cid[j]];
            lmax = fmaxf(lmax, sc[j]);
        }
        red[tid] = lmax; __syncthreads();
        for (int s = 128; s > 0; s >>= 1) { if (tid < s) red[tid] = fmaxf(red[tid], red[tid + s]); __syncthreads(); }
        float bmax = red[0]; __syncthreads();
        float lsum = 0.f;
#pragma unroll
        for (int j = 0; j < 4; j++) { sc[j] = expf(sc[j] - bmax); lsum += sc[j]; }
        red[tid] = lsum; __syncthreads();
        for (int s = 128; s > 0; s >>= 1) { if (tid < s) red[tid] += red[tid + s]; __syncthreads(); }
        float inv = 1.f / red[0]; __syncthreads();
#pragma unroll
        for (int j = 0; j < 4; j++) atomicAdd(&Wa1s[cid[j]], sc[j] * inv);
    }
    __syncthreads();
    if (tid < DD) {
        float u0 = 0.f, u1 = 0.f;
        for (int c = 0; c < NCOMBO; c++) {
            float r = d_Rtab[c * DD + tid];
            u0 += Wa0[c] * r;
            u1 += Wa1s[c] * r;
        }
        d_upd[b0 * DD + tid] = u0;
        d_upd[b1 * DD + tid] = u1;
    }
}

// 2 rows per block: halves Wk2/Wm2 re-read traffic.
__global__ void k_ukum(const float* __restrict__ Wk, const float* __restrict__ Wm) {
    int id0 = blockIdx.x * 2, id1 = id0 + 1;
    int d = threadIdx.x;
    __shared__ float s0[DD], s1[DD];
    const float* r0 = (id0 < BB) ? &d_upd[id0 * DD] : &d_embS[(id0 - BB) * DD];
    const float* r1 = (id1 < BB) ? &d_upd[id1 * DD] : &d_embS[(id1 - BB) * DD];
    if (d < DD) { s0[d] = r0[d]; s1[d] = r1[d]; }
    __syncthreads();
    if (d < DD) {
        float ak0 = 0.f, am0 = 0.f, ak1 = 0.f, am1 = 0.f;
        for (int k = 0; k < DD; k++) {
            float wk = Wk[(DD + k) * DD + d];
            float wm = Wm[(DD + k) * DD + d];
            float v0 = s0[k], v1 = s1[k];
            ak0 += v0 * wk; ak1 += v1 * wk;
            am0 += v0 * wm; am1 += v1 * wm;
        }
        d_UKall[id0 * DD + d] = ak0;
        d_UMall[id0 * DD + d] = am0;
        d_UKall[id1 * DD + d] = ak1;
        d_UMall[id1 * DD + d] = am1;
    }
}

// ------------------------- weight packing -------------------------
__global__ void k_pack(const float* __restrict__ Wk, const float* __restrict__ Wm,
                       const float* __restrict__ Wq,
                       const float* __restrict__ bk, const float* __restrict__ bm,
                       const float* __restrict__ bq,
                       const float* __restrict__ Wo1, const float* __restrict__ Wo2) {
    const float invs = 0.1414213562373095f;   // 1/sqrt(50)
    int i = blockIdx.x * blockDim.x + threadIdx.x;
    if (i < DD * 640) {
        int k = i / 640, c = i % 640;
        float v = (c < DD) ? Wk[k * DD + c]
                : (c < 2 * DD) ? Wm[k * DD + (c - DD)]
                : (c < 3 * DD) ? Wq[k * DD + (c - 2 * DD)] * invs : 0.f;
        d_Wcat[i] = v;
        return;
    }
    int j = i - DD * 640;
    if (j < DD * 256) {
        int k = j >> 8, c = j & 255;
        d_Wo1P[j] = (c < DD) ? Wo1[k * DD + c] : 0.f;
        return;
    }
    j -= DD * 256;
    if (j < DD * 256) {
        int k = j >> 8, c = j & 255;
        d_Wo2P[j] = (c < DD) ? Wo2[k * DD + c] : 0.f;
        return;
    }
    j -= DD * 256;
    if (j < 640) {
        float v = (j < DD) ? bk[j]
                : (j < 2 * DD) ? bm[j - DD]
                : (j < 3 * DD) ? bq[j - 2 * DD] * invs : 0.f;
        d_bcat[j] = v;
    }
}

// ------------------------- tf32 GEMM: 128x128 tile, 2-stage smem pipeline -------------------------
template<int DOSTAT>
__global__ __launch_bounds__(256, 2) void k_gemmT(
    int M, int Nreal, int K,
    const float* __restrict__ A, int lda,
    const float* __restrict__ B, int ldb,
    float* __restrict__ C, int ldc,
    const float* __restrict__ bias,
    const float* __restrict__ bnm, const float* __restrict__ bnr,
    const float* __restrict__ bng, const float* __restrict__ bnb) {
    __shared__ uint32_t As[2][8][132];
    __shared__ uint32_t Bs[2][8][132];
    __shared__ float cs[128], cs2[128];
    int tid = threadIdx.x;
    int lane = tid & 31, warp = tid >> 5;
    int wm = warp >> 2, wn = warp & 3;
    int gid = lane >> 2, tg = lane & 3;
    int row0 = blockIdx.y * 128, col0 = blockIdx.x * 128;
    if (DOSTAT && tid < 128) { cs[tid] = 0.f; cs2[tid] = 0.f; }

    float acc[4][4][4];
#pragma unroll
    for (int mt = 0; mt < 4; mt++)
#pragma unroll
        for (int nt = 0; nt < 4; nt++)
#pragma unroll
            for (int r = 0; r < 4; r++) acc[mt][nt][r] = 0.f;

    int rowA = row0 + (tid >> 1);
    int kA = (tid & 1) * 4;
    int rowB = tid >> 5;
    int colB = (tid & 31) * 4;
    int m0 = wm * 64, n0 = wn * 32;
    int mrow = tid >> 1;
    int nk = K / 8;

    float4 av, bv;
    {
        av = *(const float4*)&A[(size_t)rowA * lda + kA];
        if (bnm) {
            int g = kA;
            av.x = fmaxf((av.x - bnm[g])     * bnr[g]     * bng[g]     + bnb[g],     0.f);
            av.y = fmaxf((av.y - bnm[g + 1]) * bnr[g + 1] * bng[g + 1] + bnb[g + 1], 0.f);
            av.z = fmaxf((av.z - bnm[g + 2]) * bnr[g + 2] * bng[g + 2] + bnb[g + 2], 0.f);
            av.w = fmaxf((av.w - bnm[g + 3]) * bnr[g + 3] * bng[g + 3] + bnb[g + 3], 0.f);
        }
        bv = *(const float4*)&B[(size_t)rowB * ldb + col0 + colB];
        uint32_t u0, u1, u2, u3;
        CVT_TF32(u0, av.x); CVT_TF32(u1, av.y); CVT_TF32(u2, av.z); CVT_TF32(u3, av.w);
        As[0][kA + 0][mrow] = u0; As[0][kA + 1][mrow] = u1;
        As[0][kA + 2][mrow] = u2; As[0][kA + 3][mrow] = u3;
        CVT_TF32(u0, bv.x); CVT_TF32(u1, bv.y); CVT_TF32(u2, bv.z); CVT_TF32(u3, bv.w);
        Bs[0][rowB][colB] = u0; Bs[0][rowB][colB + 1] = u1;
        Bs[0][rowB][colB + 2] = u2; Bs[0][rowB][colB + 3] = u3;
    }

    for (int kt = 0; kt < nk; kt++) {
        int cur = kt & 1;
        int nxt = cur ^ 1;
        bool has = (kt + 1 < nk);
        if (has) {
            int k0 = (kt + 1) * 8;
            av = *(const float4*)&A[(size_t)rowA * lda + k0 + kA];
            if (bnm) {
                int g = k0 + kA;
                av.x = fmaxf((av.x - bnm[g])     * bnr[g]     * bng[g]     + bnb[g],     0.f);
                av.y = fmaxf((av.y - bnm[g + 1]) * bnr[g + 1] * bng[g + 1] + bnb[g + 1], 0.f);
                av.z = fmaxf((av.z - bnm[g + 2]) * bnr[g + 2] * bng[g + 2] + bnb[g + 2], 0.f);
                av.w = fmaxf((av.w - bnm[g + 3]) * bnr[g + 3] * bng[g + 3] + bnb[g + 3], 0.f);
            }
            bv = *(const float4*)&B[(size_t)(k0 + rowB) * ldb + col0 + colB];
        }
        __syncthreads();
        if (has) {
            uint32_t u0, u1, u2, u3;
            CVT_TF32(u0, av.x); CVT_TF32(u1, av.y); CVT_TF32(u2, av.z); CVT_TF32(u3, av.w);
            As[nxt][kA + 0][mrow] = u0; As[nxt][kA + 1][mrow] = u1;
            As[nxt][kA + 2][mrow] = u2; As[nxt][kA + 3][mrow] = u3;
            CVT_TF32(u0, bv.x); CVT_TF32(u1, bv.y); CVT_TF32(u2, bv.z); CVT_TF32(u3, bv.w);
            Bs[nxt][rowB][colB] = u0; Bs[nxt][rowB][colB + 1] = u1;
            Bs[nxt][rowB][colB + 2] = u2; Bs[nxt][rowB][colB + 3] = u3;
        }
        uint32_t af[4][4], bf[4][2];
#pragma unroll
        for (int mt = 0; mt < 4; mt++) {
            int mb = m0 + mt * 16 + gid;
            af[mt][0] = As[cur][tg][mb];
            af[mt][1] = As[cur][tg][mb + 8];
            af[mt][2] = As[cur][tg + 4][mb];
            af[mt][3] = As[cur][tg + 4][mb + 8];
        }
#pragma unroll
        for (int nt = 0; nt < 4; nt++) {
            int nb = n0 + nt * 8 + gid;
            bf[nt][0] = Bs[cur][tg][nb];
            bf[nt][1] = Bs[cur][tg + 4][nb];
        }
#pragma unroll
        for (int mt = 0; mt < 4; mt++)
#pragma unroll
            for (int nt = 0; nt < 4; nt++)
                MMA_TF32(acc[mt][nt][0], acc[mt][nt][1], acc[mt][nt][2], acc[mt][nt][3],
                         af[mt][0], af[mt][1], af[mt][2], af[mt][3],
                         bf[nt][0], bf[nt][1]);
    }

    float colS[4][2], colS2[4][2];
#pragma unroll
    for (int nt = 0; nt < 4; nt++) { colS[nt][0] = colS[nt][1] = 0.f; colS2[nt][0] = colS2[nt][1] = 0.f; }
#pragma unroll
    for (int mt = 0; mt < 4; mt++) {
        int r = row0 + m0 + mt * 16 + gid;
#pragma unroll
        for (int nt = 0; nt < 4; nt++) {
            int c = col0 + n0 + nt * 8 + tg * 2;
            float b0 = (bias && c < Nreal)     ? bias[c]     : 0.f;
            float b1 = (bias && c + 1 < Nreal) ? bias[c + 1] : 0.f;
            float v0 = acc[mt][nt][0] + b0;
            float v1 = acc[mt][nt][1] + b1;
            float v2 = acc[mt][nt][2] + b0;
            float v3 = acc[mt][nt][3] + b1;
            float* cr0 = &C[(size_t)r * ldc];
            float* cr1 = &C[(size_t)(r + 8) * ldc];
            if (c < Nreal)     { cr0[c] = v0; cr1[c] = v2; }
            if (c + 1 < Nreal) { cr0[c + 1] = v1; cr1[c + 1] = v3; }
            if (DOSTAT) {
                colS[nt][0]  += v0 + v2;
                colS2[nt][0] += v0 * v0 + v2 * v2;
                colS[nt][1]  += v1 + v3;
                colS2[nt][1] += v1 * v1 + v3 * v3;
            }
        }
    }
    if (DOSTAT) {
#pragma unroll
        for (int nt = 0; nt < 4; nt++) {
#pragma unroll
            for (int p = 0; p < 2; p++) {
                float a = colS[nt][p], b = colS2[nt][p];
                for (int o = 16; o >= 4; o >>= 1) {
                    a += __shfl_down_sync(0xffffffffu, a, o);
                    b += __shfl_down_sync(0xffffffffu, b, o);
                }
                colS[nt][p] = a; colS2[nt][p] = b;
            }
        }
        __syncthreads();
        if (gid == 0) {
#pragma unroll
            for (int nt = 0; nt < 4; nt++) {
                int lc = n0 + nt * 8 + tg * 2;
                atomicAdd(&cs[lc],      colS[nt][0]);
                atomicAdd(&cs2[lc],     colS2[nt][0]);
                atomicAdd(&cs[lc + 1],  colS[nt][1]);
                atomicAdd(&cs2[lc + 1], colS2[nt][1]);
            }
        }
        __syncthreads();
        if (tid < 128) {
            int gc = col0 + tid;
            if (gc < Nreal) {
                atomicAdd(&d_colsum[gc],  cs[tid]);
                atomicAdd(&d_colsum2[gc], cs2[tid]);
            }
        }
    }
}

// ------------------------- edge attention: scores + softmax denominators -------------------------
__global__ void k_D1(const int* __restrict__ ei, const int* __restrict__ ntp) {
    int warp = (blockIdx.x * blockDim.x + threadIdx.x) >> 5;
    int lane = threadIdx.x & 31;
    if (warp >= TOTROWS) return;
    int i = warp;
    int s, dd, kidx;
    if (i < EE) { s = ei[i]; dd = ei[EE + i]; kidx = i >> 10; }
    else { int n = i - EE; s = n; dd = n; kidx = BB + ntp[n]; }
    const float* kadd = &d_UKall[kidx * DD];
    const float* qrow = &d_XKMQ[(size_t)s * 600 + 400];
    const float* krow = &d_XKMQ[(size_t)dd * 600];
    int h = lane >> 3, r = lane & 7;
    float p = 0.f;
#pragma unroll
    for (int j = 0; j < 4; j++) {
        int idx = r + 8 * j;
        if (idx < 25) {
            int d0 = h * 50 + idx * 2;
            float2 q2 = *(const float2*)(qrow + d0);
            float2 k2 = *(const float2*)(krow + d0);
            float2 a2 = *(const float2*)(kadd + d0);
            p += q2.x * (k2.x + a2.x) + q2.y * (k2.y + a2.y);
        }
    }
    p += __shfl_down_sync(0xffffffffu, p, 4);
    p += __shfl_down_sync(0xffffffffu, p, 2);
    p += __shfl_down_sync(0xffffffffu, p, 1);
    if (r == 0) {
        float exv = __expf(p);
        d_ex[(size_t)i * 4 + h] = exv;
        atomicAdd(&d_den[s * 4 + h], exv);
    }
}

// ------------------------- aggregation: one warp per dst node -------------------------
__global__ __launch_bounds__(256) void k_D2w(const int* __restrict__ ei,
                                             const int* __restrict__ ntp) {
    int gw = (blockIdx.x * blockDim.x + threadIdx.x) >> 5;
    int lane = threadIdx.x & 31;
    int w = threadIdx.x >> 5;
    if (gw >= NN) return;
    int n = gw;
    int beg = d_dstOff[n], end = d_dstOff[n + 1];
    __shared__ float s_al[8][16][4];
    __shared__ int s_j[8][16], s_u[8][16];
    float acc[7];
#pragma unroll
    for (int k = 0; k < 7; k++) acc[k] = 0.f;
    for (int base = beg; base < end; base += 16) {
        int cnt = min(16, end - base);
        if (lane < cnt) {
            int i = d_csr[base + lane];
            int s, j, u;
            if (i < EE) { s = ei[i]; j = s; u = i >> 10; }
            else { int nn2 = i - EE; s = nn2; j = nn2; u = BB + ntp[nn2]; }
            s_j[w][lane] = j;
            s_u[w][lane] = u;
            float csf = (float)d_cntSrc[s];
#pragma unroll
            for (int hh = 0; hh < 4; hh++)
                s_al[w][lane][hh] = __fdividef(d_ex[(size_t)i * 4 + hh], d_den[s * 4 + hh]) * csf;
        }
        __syncwarp();
        for (int r = 0; r < cnt; r++) {
            const float* mrow = &d_XKMQ[(size_t)s_j[w][r] * 600 + 200];
            const float* urow = &d_UMall[s_u[w][r] * DD];
            float a0 = s_al[w][r][0], a1 = s_al[w][r][1];
            float a2 = s_al[w][r][2], a3 = s_al[w][r][3];
#pragma unroll
            for (int k = 0; k < 7; k++) {
                int c = lane + 32 * k;
                if (c < DD) {
                    float al = c < 50 ? a0 : c < 100 ? a1 : c < 150 ? a2 : a3;
                    acc[k] += al * (mrow[c] + urow[c]);
                }
            }
        }
        __syncwarp();
    }
#pragma unroll
    for (int k = 0; k < 7; k++) {
        int c = lane + 32 * k;
        if (c < DD) d_aggr[(size_t)n * DD + c] = acc[k];
    }
}

__global__ void k_stat3() {
    int d = threadIdx.x;
    if (d >= DD) return;
    float m = d_colsum[d] / (float)NN;
    float var = d_colsum2[d] / (float)NN - m * m;
    d_bn3m[d] = m;
    d_bn3r[d] = rsqrtf(var + 1e-5f);
}

// ------------------------- launch -------------------------
extern "C" void kernel_launch(void* const* d_in, const int* in_sizes, int n_in,
                              void* d_out, int out_size) {
    const float* x    = (const float*)d_in[0];
    const float* sent = (const float*)d_in[2];
    const float* We1  = (const float*)d_in[3];
    const float* be1  = (const float*)d_in[4];
    const float* ge1  = (const float*)d_in[5];
    const float* bte1 = (const float*)d_in[6];
    const float* We2  = (const float*)d_in[7];
    const float* be2  = (const float*)d_in[8];
    const float* Wa1  = (const float*)d_in[9];
    const float* ba1  = (const float*)d_in[10];
    const float* ga1  = (const float*)d_in[11];
    const float* bta1 = (const float*)d_in[12];
    const float* Wa2  = (const float*)d_in[13];
    const float* ba2  = (const float*)d_in[14];
    const float* Watt = (const float*)d_in[15];
    const float* Wk   = (const float*)d_in[16];
    const float* bk   = (const float*)d_in[17];
    const float* Wm   = (const float*)d_in[18];
    const float* bm   = (const float*)d_in[19];
    const float* Wq   = (const float*)d_in[20];
    const float* bq   = (const float*)d_in[21];
    const float* Wo1  = (const float*)d_in[22];
    const float* bo1  = (const float*)d_in[23];
    const float* go1  = (const float*)d_in[24];
    const float* bto1 = (const float*)d_in[25];
    const float* Wo2  = (const float*)d_in[26];
    const float* bo2  = (const float*)d_in[27];
    const int* ei     = (const int*)d_in[28];
    const int* et     = (const int*)d_in[29];
    const int* ntp    = (const int*)d_in[30];
    float* out = (float*)d_out;

    void* tmp;
    cudaGetSymbolAddress(&tmp, d_Wcat);  float* pWcat = (float*)tmp;
    cudaGetSymbolAddress(&tmp, d_bcat);  float* pbcat = (float*)tmp;
    cudaGetSymbolAddress(&tmp, d_Wo1P);  float* pWo1P = (float*)tmp;
    cudaGetSymbolAddress(&tmp, d_Wo2P);  float* pWo2P = (float*)tmp;
    cudaGetSymbolAddress(&tmp, d_XKMQ);  float* pXKMQ = (float*)tmp;
    cudaGetSymbolAddress(&tmp, d_aggr);  float* pAggr = (float*)tmp;
    cudaGetSymbolAddress(&tmp, d_Y1);    float* pY1   = (float*)tmp;
    cudaGetSymbolAddress(&tmp, d_bn3m);  float* pb3m  = (float*)tmp;
    cudaGetSymbolAddress(&tmp, d_bn3r);  float* pb3r  = (float*)tmp;

    k_zero<<<1024, 256>>>(ntp);
    k_edgehist<<<EE / 256, 256>>>(ei, et, ntp);
    k_pack<<<(DD * 640 + 2 * DD * 256 + 640 + 255) / 256, 256>>>(Wk, Wm, Wq, bk, bm, bq, Wo1, Wo2);
    k_scanA<<<50, 1024>>>();
    k_scanB<<<1, 64>>>();
    k_scanC<<<50, 1024>>>();
    k_csrfill<<<(TOTROWS + 255) / 256, 256>>>(ei);
    k_segsum3<<<400, 128>>>(x);
    k_meanT<<<(NT1 * DD + 255) / 256, 256>>>();
    k_tables<<<NCOMBO + NTY, 256>>>(We1, be1);
    k_bnstat1p<<<DD, 128>>>();
    k_emb<<<(NCOMBO + NTY) / 2, 256>>>(We2, be2, ge1, bte1);
    k_h2pre<<<NCOMBO / 2, 256>>>(Wa1, ba1);
    k_bnstat2p<<<DD, 128>>>();
    k_Rtab<<<NCOMBO / 2, 256>>>(Wa2, ba2, ga1, bta1);
    k_attn<<<BB / 2, 256>>>(sent, Watt);
    k_ukum<<<(BB + NTY) / 2, 256>>>(Wk, Wm);
    {   // XKMQ = x @ [Wk1|Wm1|Wq*invs] + [bk|bm|bq*invs]
        dim3 g(5, NN / 128);
        k_gemmT<0><<<g, 256>>>(NN, 600, DD, x, DD, pWcat, 640, pXKMQ, 600,
                               pbcat, nullptr, nullptr, nullptr, nullptr);
    }
    k_D1<<<(TOTROWS + 7) / 8, 256>>>(ei, ntp);
    k_D2w<<<NN / 8, 256>>>(ei, ntp);
    {   // Y1 = aggr @ Wo1 + bo1  (+ fused column stats)
        dim3 g(2, NN / 128);
        k_gemmT<1><<<g, 256>>>(NN, DD, DD, pAggr, DD, pWo1P, 256, pY1, DD,
                               bo1, nullptr, nullptr, nullptr, nullptr);
    }
    k_stat3<<<1, 256>>>();
    {   // out = relu(bn(Y1)) @ Wo2 + bo2
        dim3 g(2, NN / 128);
        k_gemmT<0><<<g, 256>>>(NN, DD, DD, pY1, DD, pWo2P, 256, out, DD,
                               bo2, pb3m, pb3r, go1, bto1);
    }
}

// round 9
// speedup vs baseline: 1.3474x; 1.1050x over previous
#include <cuda_runtime.h>
#include <math.h>
#include <stdint.h>

#define DD 200
#define NTY 4
#define NET 38
#define NT1 39
#define BB 256
#define LL 1024
#define EE 262144
#define NN 51200
#define NCOMBO 608
#define TOTROWS (EE + NN)

// f32x2 packed-math helpers
#define FMA2(d,a,b)  asm("fma.rn.f32x2 %0, %1, %2, %3;" : "=l"(d) : "l"(a), "l"(b), "l"(d))
#define PACK2(d,x,y) asm("mov.b64 %0, {%1, %2};" : "=l"(d) : "f"(x), "f"(y))
#define UNPACK2(x,y,d) asm("mov.b64 {%0, %1}, %2;" : "=f"(x), "=f"(y) : "l"(d))

#define CVT_TF32(u,f) asm("cvt.rna.tf32.f32 %0, %1;" : "=r"(u) : "f"(f))
#define MMA_TF32(c0,c1,c2,c3,a0,a1,a2,a3,b0,b1) \
  asm("mma.sync.aligned.m16n8k8.row.col.f32.tf32.tf32.f32 " \
      "{%0,%1,%2,%3},{%4,%5,%6,%7},{%8,%9},{%0,%1,%2,%3};" \
      : "+f"(c0),"+f"(c1),"+f"(c2),"+f"(c3) \
      : "r"(a0),"r"(a1),"r"(a2),"r"(a3),"r"(b0),"r"(b1))

// ------------------------- scratch -------------------------
__device__ float d_coeff[(size_t)NN * NT1];
__device__ float d_sums[NT1 * DD];
__device__ int   d_cntT[NT1];
__device__ int   d_cntE[NCOMBO];
__device__ int   d_cntN[NTY];
__device__ int   d_combo[EE];
__device__ int   d_cntSrc[NN];
__device__ int   d_dstCnt[NN];
__device__ int   d_dstOff[NN + 1];
__device__ int   d_cursor[NN];
__device__ int   d_csr[TOTROWS];
__device__ int   d_blkSum[50];
__device__ float d_meanT[NT1 * DD];
__device__ float d_preE[NCOMBO * DD];
__device__ float d_preS[NTY * DD];
__device__ float d_embE[NCOMBO * DD];
__device__ float d_embS[NTY * DD];
__device__ float d_h2[NCOMBO * DD];
__device__ float d_Rtab[NCOMBO * DD];
__device__ float d_bn1m[DD], d_bn1r[DD], d_bn2m[DD], d_bn2r[DD], d_bn3m[DD], d_bn3r[DD];
__device__ float d_upd[BB * DD];
__device__ float d_UKall[(BB + NTY) * DD];
__device__ float d_UMall[(BB + NTY) * DD];
__device__ float d_Wcat[DD * 640];
__device__ float d_bcat[640];
__device__ float d_Wo1P[DD * 256];
__device__ float d_Wo2P[DD * 256];
__device__ float d_XKMQ[(size_t)NN * 600];    // per-node [XK+bk | XM+bm | (XQ+bq)*invs]
__device__ float d_ex[(size_t)TOTROWS * 4];
__device__ float d_den[NN * 4];
__device__ float d_aggr[(size_t)NN * DD];
__device__ float d_Y1[(size_t)NN * DD];
__device__ float d_colsum[DD], d_colsum2[DD];

// ------------------------- zero init + node hist (fused) -------------------------
__global__ void k_zero(const int* __restrict__ ntp) {
    long long i0 = (long long)blockIdx.x * blockDim.x + threadIdx.x;
    long long st = (long long)gridDim.x * blockDim.x;
    for (long long i = i0; i < (long long)NT1 * NN; i += st) d_coeff[i] = 0.f;
    for (long long i = i0; i < (long long)NN * 4; i += st) d_den[i] = 0.f;
    for (long long i = i0; i < NT1 * DD; i += st) d_sums[i] = 0.f;
    for (long long i = i0; i < NCOMBO; i += st) d_cntE[i] = 0;
    for (long long i = i0; i < NT1; i += st) d_cntT[i] = 0;
    for (long long i = i0; i < NTY; i += st) d_cntN[i] = 0;
    for (long long i = i0; i < DD; i += st) { d_colsum[i] = 0.f; d_colsum2[i] = 0.f; }
    for (long long i = i0; i < NN; i += st) {
        d_cntSrc[i] = 1;
        d_dstCnt[i] = 1;
        atomicAdd(&d_cntN[ntp[i]], 1);
    }
}

// smem histograms for the hot 39/608-bin counters
__global__ void k_edgehist(const int* __restrict__ ei, const int* __restrict__ et,
                           const int* __restrict__ ntp) {
    __shared__ int sT[NT1];
    __shared__ int sE[NCOMBO];
    int tid = threadIdx.x;
    for (int i = tid; i < NT1; i += 256) sT[i] = 0;
    for (int i = tid; i < NCOMBO; i += 256) sE[i] = 0;
    __syncthreads();
    int e = blockIdx.x * 256 + tid;
    int s  = ei[e];
    int dd = ei[EE + e];
    int t  = et[e];
    atomicAdd(&d_coeff[(size_t)dd * NT1 + t],  1.f);
    atomicAdd(&d_coeff[(size_t)s  * NT1 + t], -1.f);
    atomicAdd(&sT[t], 1);
    int c = (t << 4) | (ntp[s] << 2) | ntp[dd];
    d_combo[e] = c;
    atomicAdd(&sE[c], 1);
    atomicAdd(&d_cntSrc[s], 1);
    atomicAdd(&d_dstCnt[dd], 1);
    __syncthreads();
    for (int i = tid; i < NT1; i += 256) if (sT[i]) atomicAdd(&d_cntT[i], sT[i]);
    for (int i = tid; i < NCOMBO; i += 256) if (sE[i]) atomicAdd(&d_cntE[i], sE[i]);
}

// ------------------------- dst-CSR build (3-phase parallel scan) -------------------------
__global__ void k_scanA() {
    __shared__ int sm[1024];
    int tid = threadIdx.x;
    sm[tid] = d_dstCnt[blockIdx.x * 1024 + tid];
    __syncthreads();
    for (int o = 512; o > 0; o >>= 1) {
        if (tid < o) sm[tid] += sm[tid + o];
        __syncthreads();
    }
    if (tid == 0) d_blkSum[blockIdx.x] = sm[0];
}

__global__ void k_scanB() {
    __shared__ int sm[64];
    int tid = threadIdx.x;
    int v = (tid < 50) ? d_blkSum[tid] : 0;
    sm[tid] = v;
    __syncthreads();
    for (int o = 1; o < 64; o <<= 1) {
        int t = (tid >= o) ? sm[tid - o] : 0;
        __syncthreads();
        sm[tid] += t;
        __syncthreads();
    }
    if (tid < 50) d_blkSum[tid] = sm[tid] - v;
    if (tid == 49) d_dstOff[NN] = sm[49];
}

__global__ void k_scanC() {
    __shared__ int sm[1024];
    int tid = threadIdx.x;
    int g = blockIdx.x * 1024 + tid;
    int v = d_dstCnt[g];
    sm[tid] = v;
    __syncthreads();
    for (int o = 1; o < 1024; o <<= 1) {
        int t = (tid >= o) ? sm[tid - o] : 0;
        __syncthreads();
        sm[tid] += t;
        __syncthreads();
    }
    int excl = sm[tid] - v + d_blkSum[blockIdx.x];
    d_dstOff[g] = excl;
    d_cursor[g] = excl;
}

__global__ void k_csrfill(const int* __restrict__ ei) {
    int i = blockIdx.x * blockDim.x + threadIdx.x;
    if (i >= TOTROWS) return;
    int dst = (i < EE) ? ei[EE + i] : (i - EE);
    int pos = atomicAdd(&d_cursor[dst], 1);
    d_csr[pos] = i;
}

// ------------------------- segment sums -------------------------
__global__ __launch_bounds__(128) void k_segsum3(const float* __restrict__ x) {
    __shared__ unsigned long long cf2[128][NT1];
    int tid = threadIdx.x;
    int n0 = blockIdx.x * 128;
    for (int i = tid; i < 128 * NT1; i += 128) {
        float c = d_coeff[(size_t)(n0 + i / NT1) * NT1 + (i % NT1)];
        unsigned long long c2; PACK2(c2, c, c);
        cf2[i / NT1][i % NT1] = c2;
    }
    __syncthreads();
    if (tid < 100) {
        unsigned long long acc[NT1];
#pragma unroll
        for (int t = 0; t < NT1; t++) acc[t] = 0ULL;
        for (int nn = 0; nn < 128; nn++) {
            float2 xv = *(const float2*)&x[(size_t)(n0 + nn) * DD + tid * 2];
            unsigned long long xv2; PACK2(xv2, xv.x, xv.y);
#pragma unroll
            for (int t = 0; t < NT1; t++)
                FMA2(acc[t], cf2[nn][t], xv2);
        }
#pragma unroll
        for (int t = 0; t < NT1; t++) {
            float lo, hi; UNPACK2(lo, hi, acc[t]);
            if (lo != 0.f) atomicAdd(&d_sums[t * DD + tid * 2], lo);
            if (hi != 0.f) atomicAdd(&d_sums[t * DD + tid * 2 + 1], hi);
        }
    }
}

__global__ void k_meanT() {
    int i = blockIdx.x * blockDim.x + threadIdx.x;
    if (i >= NT1 * DD) return;
    int t = i / DD;
    float c = (float)d_cntT[t];
    if (c < 1.f) c = 1.f;
    d_meanT[i] = d_sums[i] / c;
}

// ------------------------- combo tables -------------------------
__global__ void k_tables(const float* __restrict__ We1, const float* __restrict__ be1) {
    int c = blockIdx.x, d = threadIdx.x;
    if (d >= DD) return;
    if (c < NCOMBO) {
        int t = c >> 4, a = (c >> 2) & 3, b = c & 3;
        d_preE[c * DD + d] = We1[t * DD + d] + We1[(NT1 + a) * DD + d]
                           + We1[(NT1 + NTY + b) * DD + d] + be1[d];
    } else {
        int t = c - NCOMBO;
        d_preS[t * DD + d] = We1[NET * DD + d] + We1[(NT1 + t) * DD + d]
                           + We1[(NT1 + NTY + t) * DD + d] + be1[d];
    }
}

__global__ void k_bnstat1p() {
    int d = blockIdx.x, tid = threadIdx.x;
    __shared__ double rs[128], rs2[128];
    double s = 0.0, s2 = 0.0;
    for (int c = tid; c < NCOMBO; c += 128) {
        double w = (double)d_cntE[c], v = (double)d_preE[c * DD + d];
        s += w * v; s2 += w * v * v;
    }
    if (tid < NTY) {
        double w = (double)d_cntN[tid], v = (double)d_preS[tid * DD + d];
        s += w * v; s2 += w * v * v;
    }
    rs[tid] = s; rs2[tid] = s2;
    __syncthreads();
    for (int o = 64; o > 0; o >>= 1) {
        if (tid < o) { rs[tid] += rs[tid + o]; rs2[tid] += rs2[tid + o]; }
        __syncthreads();
    }
    if (tid == 0) {
        double m = rs[0] / (double)TOTROWS;
        double var = rs2[0] / (double)TOTROWS - m * m;
        d_bn1m[d] = (float)m;
        d_bn1r[d] = rsqrtf((float)var + 1e-5f);
    }
}

__global__ void k_emb(const float* __restrict__ We2, const float* __restrict__ be2,
                      const float* __restrict__ g, const float* __restrict__ bt) {
    int c = blockIdx.x, d = threadIdx.x;
    __shared__ float a[DD];
    const float* srow = (c < NCOMBO) ? &d_preE[c * DD] : &d_preS[(c - NCOMBO) * DD];
    if (d < DD) {
        float v = (srow[d] - d_bn1m[d]) * d_bn1r[d] * g[d] + bt[d];
        a[d] = fmaxf(v, 0.f);
    }
    __syncthreads();
    if (d < DD) {
        float acc = 0.f;
        for (int k = 0; k < DD; k++) acc += a[k] * We2[k * DD + d];
        float* dst = (c < NCOMBO) ? &d_embE[c * DD] : &d_embS[(c - NCOMBO) * DD];
        dst[d] = acc + be2[d];
    }
}

__global__ void k_h2pre(const float* __restrict__ Wa1, const float* __restrict__ ba1) {
    int c = blockIdx.x, d = threadIdx.x;
    __shared__ float e[DD], mt[DD];
    int t = c >> 4;
    if (d < DD) { e[d] = d_embE[c * DD + d]; mt[d] = d_meanT[t * DD + d]; }
    __syncthreads();
    if (d < DD) {
        float acc = ba1[d];
        for (int k = 0; k < DD; k++) acc += e[k] * Wa1[k * DD + d];
        for (int k = 0; k < DD; k++) acc += mt[k] * Wa1[(DD + k) * DD + d];
        d_h2[c * DD + d] = acc;
    }
}

__global__ void k_bnstat2p() {
    int d = blockIdx.x, tid = threadIdx.x;
    __shared__ double rs[128], rs2[128];
    double s = 0.0, s2 = 0.0;
    for (int c = tid; c < NCOMBO; c += 128) {
        double w = (double)d_cntE[c], v = (double)d_h2[c * DD + d];
        s += w * v; s2 += w * v * v;
    }
    rs[tid] = s; rs2[tid] = s2;
    __syncthreads();
    for (int o = 64; o > 0; o >>= 1) {
        if (tid < o) { rs[tid] += rs[tid + o]; rs2[tid] += rs2[tid + o]; }
        __syncthreads();
    }
    if (tid == 0) {
        double m = rs[0] / (double)EE;
        double var = rs2[0] / (double)EE - m * m;
        d_bn2m[d] = (float)m;
        d_bn2r[d] = rsqrtf((float)var + 1e-5f);
    }
}

__global__ void k_Rtab(const float* __restrict__ Wa2, const float* __restrict__ ba2,
                       const float* __restrict__ g, const float* __restrict__ bt) {
    int c = blockIdx.x, d = threadIdx.x;
    __shared__ float a[DD];
    if (d < DD) {
        float v = (d_h2[c * DD + d] - d_bn2m[d]) * d_bn2r[d] * g[d] + bt[d];
        a[d] = fmaxf(v, 0.f);
    }
    __syncthreads();
    if (d < DD) {
        float acc = 0.f;
        for (int k = 0; k < DD; k++) acc += a[k] * Wa2[k * DD + d];
        d_Rtab[c * DD + d] = acc + ba2[d];
    }
}

// ------------------------- fused graph attention -------------------------
__global__ __launch_bounds__(256) void k_attn(const float* __restrict__ sent,
                                              const float* __restrict__ Watt) {
    int b = blockIdx.x, tid = threadIdx.x;
    __shared__ float sv[DD], q[DD];
    __shared__ float Pb[NCOMBO], Wacc[NCOMBO];
    __shared__ float red[256];
    if (tid < DD) sv[tid] = sent[b * DD + tid];
    for (int i = tid; i < NCOMBO; i += 256) Wacc[i] = 0.f;
    __syncthreads();
    if (tid < DD) {
        float a = 0.f;
        for (int k = 0; k < DD; k++) a += sv[k] * Watt[k * DD + tid];
        q[tid] = a * 0.07071067811865475f;   // 1/sqrt(200)
    }
    __syncthreads();
    int lane = tid & 31, w = tid >> 5;
    for (int c = w; c < NCOMBO; c += 8) {
        float p = 0.f;
        for (int k = lane; k < DD; k += 32) p += q[k] * d_Rtab[c * DD + k];
        for (int o = 16; o > 0; o >>= 1) p += __shfl_down_sync(0xffffffffu, p, o);
        if (lane == 0) Pb[c] = p;
    }
    __syncthreads();
    int cid[4]; float sc[4]; float lmax = -1e30f;
#pragma unroll
    for (int j = 0; j < 4; j++) {
        int e = b * LL + tid + j * 256;
        cid[j] = d_combo[e];
        sc[j] = Pb[cid[j]];
        lmax = fmaxf(lmax, sc[j]);
    }
    red[tid] = lmax; __syncthreads();
    for (int s = 128; s > 0; s >>= 1) { if (tid < s) red[tid] = fmaxf(red[tid], red[tid + s]); __syncthreads(); }
    float bmax = red[0]; __syncthreads();
    float lsum = 0.f;
#pragma unroll
    for (int j = 0; j < 4; j++) { sc[j] = expf(sc[j] - bmax); lsum += sc[j]; }
    red[tid] = lsum; __syncthreads();
    for (int s = 128; s > 0; s >>= 1) { if (tid < s) red[tid] += red[tid + s]; __syncthreads(); }
    float inv = 1.f / red[0]; __syncthreads();
#pragma unroll
    for (int j = 0; j < 4; j++) atomicAdd(&Wacc[cid[j]], sc[j] * inv);
    __syncthreads();
    if (tid < DD) {
        float a = 0.f;
        for (int c = 0; c < NCOMBO; c++) a += Wacc[c] * d_Rtab[c * DD + tid];
        d_upd[b * DD + tid] = a;
    }
}

__global__ void k_ukum(const float* __restrict__ Wk, const float* __restrict__ Wm) {
    int id = blockIdx.x, d = threadIdx.x;
    __shared__ float s[DD];
    const float* srow = (id < BB) ? &d_upd[id * DD] : &d_embS[(id - BB) * DD];
    if (d < DD) s[d] = srow[d];
    __syncthreads();
    if (d < DD) {
        float ak = 0.f, am = 0.f;
        for (int k = 0; k < DD; k++) {
            float sv = s[k];
            ak += sv * Wk[(DD + k) * DD + d];
            am += sv * Wm[(DD + k) * DD + d];
        }
        d_UKall[id * DD + d] = ak;
        d_UMall[id * DD + d] = am;
    }
}

// ------------------------- weight packing -------------------------
__global__ void k_pack(const float* __restrict__ Wk, const float* __restrict__ Wm,
                       const float* __restrict__ Wq,
                       const float* __restrict__ bk, const float* __restrict__ bm,
                       const float* __restrict__ bq,
                       const float* __restrict__ Wo1, const float* __restrict__ Wo2) {
    const float invs = 0.1414213562373095f;   // 1/sqrt(50)
    int i = blockIdx.x * blockDim.x + threadIdx.x;
    if (i < DD * 640) {
        int k = i / 640, c = i % 640;
        float v = (c < DD) ? Wk[k * DD + c]
                : (c < 2 * DD) ? Wm[k * DD + (c - DD)]
                : (c < 3 * DD) ? Wq[k * DD + (c - 2 * DD)] * invs : 0.f;
        d_Wcat[i] = v;
        return;
    }
    int j = i - DD * 640;
    if (j < DD * 256) {
        int k = j >> 8, c = j & 255;
        d_Wo1P[j] = (c < DD) ? Wo1[k * DD + c] : 0.f;
        return;
    }
    j -= DD * 256;
    if (j < DD * 256) {
        int k = j >> 8, c = j & 255;
        d_Wo2P[j] = (c < DD) ? Wo2[k * DD + c] : 0.f;
        return;
    }
    j -= DD * 256;
    if (j < 640) {
        float v = (j < DD) ? bk[j]
                : (j < 2 * DD) ? bm[j - DD]
                : (j < 3 * DD) ? bq[j - 2 * DD] * invs : 0.f;
        d_bcat[j] = v;
    }
}

// ------------------------- tf32 GEMM: 128x128 tile, 2-stage smem pipeline -------------------------
template<int DOSTAT>
__global__ __launch_bounds__(256, 2) void k_gemmT(
    int M, int Nreal, int K,
    const float* __restrict__ A, int lda,
    const float* __restrict__ B, int ldb,
    float* __restrict__ C, int ldc,
    const float* __restrict__ bias,
    const float* __restrict__ bnm, const float* __restrict__ bnr,
    const float* __restrict__ bng, const float* __restrict__ bnb) {
    __shared__ uint32_t As[2][8][132];
    __shared__ uint32_t Bs[2][8][132];
    __shared__ float cs[128], cs2[128];
    int tid = threadIdx.x;
    int lane = tid & 31, warp = tid >> 5;
    int wm = warp >> 2, wn = warp & 3;
    int gid = lane >> 2, tg = lane & 3;
    int row0 = blockIdx.y * 128, col0 = blockIdx.x * 128;
    if (DOSTAT && tid < 128) { cs[tid] = 0.f; cs2[tid] = 0.f; }

    float acc[4][4][4];
#pragma unroll
    for (int mt = 0; mt < 4; mt++)
#pragma unroll
        for (int nt = 0; nt < 4; nt++)
#pragma unroll
            for (int r = 0; r < 4; r++) acc[mt][nt][r] = 0.f;

    int rowA = row0 + (tid >> 1);
    int kA = (tid & 1) * 4;
    int rowB = tid >> 5;
    int colB = (tid & 31) * 4;
    int m0 = wm * 64, n0 = wn * 32;
    int mrow = tid >> 1;
    int nk = K / 8;

    float4 av, bv;
    {
        av = *(const float4*)&A[(size_t)rowA * lda + kA];
        if (bnm) {
            int g = kA;
            av.x = fmaxf((av.x - bnm[g])     * bnr[g]     * bng[g]     + bnb[g],     0.f);
            av.y = fmaxf((av.y - bnm[g + 1]) * bnr[g + 1] * bng[g + 1] + bnb[g + 1], 0.f);
            av.z = fmaxf((av.z - bnm[g + 2]) * bnr[g + 2] * bng[g + 2] + bnb[g + 2], 0.f);
            av.w = fmaxf((av.w - bnm[g + 3]) * bnr[g + 3] * bng[g + 3] + bnb[g + 3], 0.f);
        }
        bv = *(const float4*)&B[(size_t)rowB * ldb + col0 + colB];
        uint32_t u0, u1, u2, u3;
        CVT_TF32(u0, av.x); CVT_TF32(u1, av.y); CVT_TF32(u2, av.z); CVT_TF32(u3, av.w);
        As[0][kA + 0][mrow] = u0; As[0][kA + 1][mrow] = u1;
        As[0][kA + 2][mrow] = u2; As[0][kA + 3][mrow] = u3;
        CVT_TF32(u0, bv.x); CVT_TF32(u1, bv.y); CVT_TF32(u2, bv.z); CVT_TF32(u3, bv.w);
        Bs[0][rowB][colB] = u0; Bs[0][rowB][colB + 1] = u1;
        Bs[0][rowB][colB + 2] = u2; Bs[0][rowB][colB + 3] = u3;
    }

    for (int kt = 0; kt < nk; kt++) {
        int cur = kt & 1;
        int nxt = cur ^ 1;
        bool has = (kt + 1 < nk);
        if (has) {
            int k0 = (kt + 1) * 8;
            av = *(const float4*)&A[(size_t)rowA * lda + k0 + kA];
            if (bnm) {
                int g = k0 + kA;
                av.x = fmaxf((av.x - bnm[g])     * bnr[g]     * bng[g]     + bnb[g],     0.f);
                av.y = fmaxf((av.y - bnm[g + 1]) * bnr[g + 1] * bng[g + 1] + bnb[g + 1], 0.f);
                av.z = fmaxf((av.z - bnm[g + 2]) * bnr[g + 2] * bng[g + 2] + bnb[g + 2], 0.f);
                av.w = fmaxf((av.w - bnm[g + 3]) * bnr[g + 3] * bng[g + 3] + bnb[g + 3], 0.f);
            }
            bv = *(const float4*)&B[(size_t)(k0 + rowB) * ldb + col0 + colB];
        }
        __syncthreads();
        if (has) {
            uint32_t u0, u1, u2, u3;
            CVT_TF32(u0, av.x); CVT_TF32(u1, av.y); CVT_TF32(u2, av.z); CVT_TF32(u3, av.w);
            As[nxt][kA + 0][mrow] = u0; As[nxt][kA + 1][mrow] = u1;
            As[nxt][kA + 2][mrow] = u2; As[nxt][kA + 3][mrow] = u3;
            CVT_TF32(u0, bv.x); CVT_TF32(u1, bv.y); CVT_TF32(u2, bv.z); CVT_TF32(u3, bv.w);
            Bs[nxt][rowB][colB] = u0; Bs[nxt][rowB][colB + 1] = u1;
            Bs[nxt][rowB][colB + 2] = u2; Bs[nxt][rowB][colB + 3] = u3;
        }
        uint32_t af[4][4], bf[4][2];
#pragma unroll
        for (int mt = 0; mt < 4; mt++) {
            int mb = m0 + mt * 16 + gid;
            af[mt][0] = As[cur][tg][mb];
            af[mt][1] = As[cur][tg][mb + 8];
            af[mt][2] = As[cur][tg + 4][mb];
            af[mt][3] = As[cur][tg + 4][mb + 8];
        }
#pragma unroll
        for (int nt = 0; nt < 4; nt++) {
            int nb = n0 + nt * 8 + gid;
            bf[nt][0] = Bs[cur][tg][nb];
            bf[nt][1] = Bs[cur][tg + 4][nb];
        }
#pragma unroll
        for (int mt = 0; mt < 4; mt++)
#pragma unroll
            for (int nt = 0; nt < 4; nt++)
                MMA_TF32(acc[mt][nt][0], acc[mt][nt][1], acc[mt][nt][2], acc[mt][nt][3],
                         af[mt][0], af[mt][1], af[mt][2], af[mt][3],
                         bf[nt][0], bf[nt][1]);
    }

    float colS[4][2], colS2[4][2];
#pragma unroll
    for (int nt = 0; nt < 4; nt++) { colS[nt][0] = colS[nt][1] = 0.f; colS2[nt][0] = colS2[nt][1] = 0.f; }
#pragma unroll
    for (int mt = 0; mt < 4; mt++) {
        int r = row0 + m0 + mt * 16 + gid;
#pragma unroll
        for (int nt = 0; nt < 4; nt++) {
            int c = col0 + n0 + nt * 8 + tg * 2;
            float b0 = (bias && c < Nreal)     ? bias[c]     : 0.f;
            float b1 = (bias && c + 1 < Nreal) ? bias[c + 1] : 0.f;
            float v0 = acc[mt][nt][0] + b0;
            float v1 = acc[mt][nt][1] + b1;
            float v2 = acc[mt][nt][2] + b0;
            float v3 = acc[mt][nt][3] + b1;
            float* cr0 = &C[(size_t)r * ldc];
            float* cr1 = &C[(size_t)(r + 8) * ldc];
            if (c < Nreal)     { cr0[c] = v0; cr1[c] = v2; }
            if (c + 1 < Nreal) { cr0[c + 1] = v1; cr1[c + 1] = v3; }
            if (DOSTAT) {
                colS[nt][0]  += v0 + v2;
                colS2[nt][0] += v0 * v0 + v2 * v2;
                colS[nt][1]  += v1 + v3;
                colS2[nt][1] += v1 * v1 + v3 * v3;
            }
        }
    }
    if (DOSTAT) {
#pragma unroll
        for (int nt = 0; nt < 4; nt++) {
#pragma unroll
            for (int p = 0; p < 2; p++) {
                float a = colS[nt][p], b = colS2[nt][p];
                for (int o = 16; o >= 4; o >>= 1) {
                    a += __shfl_down_sync(0xffffffffu, a, o);
                    b += __shfl_down_sync(0xffffffffu, b, o);
                }
                colS[nt][p] = a; colS2[nt][p] = b;
            }
        }
        __syncthreads();
        if (gid == 0) {
#pragma unroll
            for (int nt = 0; nt < 4; nt++) {
                int lc = n0 + nt * 8 + tg * 2;
                atomicAdd(&cs[lc],      colS[nt][0]);
                atomicAdd(&cs2[lc],     colS2[nt][0]);
                atomicAdd(&cs[lc + 1],  colS[nt][1]);
                atomicAdd(&cs2[lc + 1], colS2[nt][1]);
            }
        }
        __syncthreads();
        if (tid < 128) {
            int gc = col0 + tid;
            if (gc < Nreal) {
                atomicAdd(&d_colsum[gc],  cs[tid]);
                atomicAdd(&d_colsum2[gc], cs2[tid]);
            }
        }
    }
}

// ------------------------- edge attention: scores + softmax denominators -------------------------
__global__ void k_D1(const int* __restrict__ ei, const int* __restrict__ ntp) {
    int warp = (blockIdx.x * blockDim.x + threadIdx.x) >> 5;
    int lane = threadIdx.x & 31;
    if (warp >= TOTROWS) return;
    int i = warp;
    int s, dd, kidx;
    if (i < EE) { s = ei[i]; dd = ei[EE + i]; kidx = i >> 10; }
    else { int n = i - EE; s = n; dd = n; kidx = BB + ntp[n]; }
    const float* kadd = &d_UKall[kidx * DD];
    const float* qrow = &d_XKMQ[(size_t)s * 600 + 400];
    const float* krow = &d_XKMQ[(size_t)dd * 600];
    int h = lane >> 3, r = lane & 7;
    float p = 0.f;
#pragma unroll
    for (int j = 0; j < 4; j++) {
        int idx = r + 8 * j;
        if (idx < 25) {
            int d0 = h * 50 + idx * 2;
            float2 q2 = *(const float2*)(qrow + d0);
            float2 k2 = *(const float2*)(krow + d0);
            float2 a2 = *(const float2*)(kadd + d0);
            p += q2.x * (k2.x + a2.x) + q2.y * (k2.y + a2.y);
        }
    }
    p += __shfl_down_sync(0xffffffffu, p, 4);
    p += __shfl_down_sync(0xffffffffu, p, 2);
    p += __shfl_down_sync(0xffffffffu, p, 1);
    if (r == 0) {
        float exv = __expf(p);
        d_ex[(size_t)i * 4 + h] = exv;
        atomicAdd(&d_den[s * 4 + h], exv);
    }
}

// ------------------------- aggregation: one warp per dst node -------------------------
__global__ __launch_bounds__(256) void k_D2w(const int* __restrict__ ei,
                                             const int* __restrict__ ntp) {
    int gw = (blockIdx.x * blockDim.x + threadIdx.x) >> 5;
    int lane = threadIdx.x & 31;
    int w = threadIdx.x >> 5;
    if (gw >= NN) return;
    int n = gw;
    int beg = d_dstOff[n], end = d_dstOff[n + 1];
    __shared__ float s_al[8][16][4];
    __shared__ int s_j[8][16], s_u[8][16];
    float acc[7];
#pragma unroll
    for (int k = 0; k < 7; k++) acc[k] = 0.f;
    for (int base = beg; base < end; base += 16) {
        int cnt = min(16, end - base);
        if (lane < cnt) {
            int i = d_csr[base + lane];
            int s, j, u;
            if (i < EE) { s = ei[i]; j = s; u = i >> 10; }
            else { int nn2 = i - EE; s = nn2; j = nn2; u = BB + ntp[nn2]; }
            s_j[w][lane] = j;
            s_u[w][lane] = u;
            float csf = (float)d_cntSrc[s];
#pragma unroll
            for (int hh = 0; hh < 4; hh++)
                s_al[w][lane][hh] = __fdividef(d_ex[(size_t)i * 4 + hh], d_den[s * 4 + hh]) * csf;
        }
        __syncwarp();
        for (int r = 0; r < cnt; r++) {
            const float* mrow = &d_XKMQ[(size_t)s_j[w][r] * 600 + 200];
            const float* urow = &d_UMall[s_u[w][r] * DD];
            float a0 = s_al[w][r][0], a1 = s_al[w][r][1];
            float a2 = s_al[w][r][2], a3 = s_al[w][r][3];
#pragma unroll
            for (int k = 0; k < 7; k++) {
                int c = lane + 32 * k;
                if (c < DD) {
                    float al = c < 50 ? a0 : c < 100 ? a1 : c < 150 ? a2 : a3;
                    acc[k] += al * (mrow[c] + urow[c]);
                }
            }
        }
        __syncwarp();
    }
#pragma unroll
    for (int k = 0; k < 7; k++) {
        int c = lane + 32 * k;
        if (c < DD) d_aggr[(size_t)n * DD + c] = acc[k];
    }
}

__global__ void k_stat3() {
    int d = threadIdx.x;
    if (d >= DD) return;
    float m = d_colsum[d] / (float)NN;
    float var = d_colsum2[d] / (float)NN - m * m;
    d_bn3m[d] = m;
    d_bn3r[d] = rsqrtf(var + 1e-5f);
}

// ------------------------- launch (forked graph: GEMM / CSR / table-chain in parallel) -------------------------
extern "C" void kernel_launch(void* const* d_in, const int* in_sizes, int n_in,
                              void* d_out, int out_size) {
    const float* x    = (const float*)d_in[0];
    const float* sent = (const float*)d_in[2];
    const float* We1  = (const float*)d_in[3];
    const float* be1  = (const float*)d_in[4];
    const float* ge1  = (const float*)d_in[5];
    const float* bte1 = (const float*)d_in[6];
    const float* We2  = (const float*)d_in[7];
    const float* be2  = (const float*)d_in[8];
    const float* Wa1  = (const float*)d_in[9];
    const float* ba1  = (const float*)d_in[10];
    const float* ga1  = (const float*)d_in[11];
    const float* bta1 = (const float*)d_in[12];
    const float* Wa2  = (const float*)d_in[13];
    const float* ba2  = (const float*)d_in[14];
    const float* Watt = (const float*)d_in[15];
    const float* Wk   = (const float*)d_in[16];
    const float* bk   = (const float*)d_in[17];
    const float* Wm   = (const float*)d_in[18];
    const float* bm   = (const float*)d_in[19];
    const float* Wq   = (const float*)d_in[20];
    const float* bq   = (const float*)d_in[21];
    const float* Wo1  = (const float*)d_in[22];
    const float* bo1  = (const float*)d_in[23];
    const float* go1  = (const float*)d_in[24];
    const float* bto1 = (const float*)d_in[25];
    const float* Wo2  = (const float*)d_in[26];
    const float* bo2  = (const float*)d_in[27];
    const int* ei     = (const int*)d_in[28];
    const int* et     = (const int*)d_in[29];
    const int* ntp    = (const int*)d_in[30];
    float* out = (float*)d_out;

    void* tmp;
    cudaGetSymbolAddress(&tmp, d_Wcat);  float* pWcat = (float*)tmp;
    cudaGetSymbolAddress(&tmp, d_bcat);  float* pbcat = (float*)tmp;
    cudaGetSymbolAddress(&tmp, d_Wo1P);  float* pWo1P = (float*)tmp;
    cudaGetSymbolAddress(&tmp, d_Wo2P);  float* pWo2P = (float*)tmp;
    cudaGetSymbolAddress(&tmp, d_XKMQ);  float* pXKMQ = (float*)tmp;
    cudaGetSymbolAddress(&tmp, d_aggr);  float* pAggr = (float*)tmp;
    cudaGetSymbolAddress(&tmp, d_Y1);    float* pY1   = (float*)tmp;
    cudaGetSymbolAddress(&tmp, d_bn3m);  float* pb3m  = (float*)tmp;
    cudaGetSymbolAddress(&tmp, d_bn3r);  float* pb3r  = (float*)tmp;

    static cudaStream_t sA = nullptr, sB = nullptr;
    static cudaEvent_t evStart = nullptr, evH = nullptr, evA = nullptr, evB = nullptr;
    if (!sA) {
        cudaStreamCreateWithFlags(&sA, cudaStreamNonBlocking);
        cudaStreamCreateWithFlags(&sB, cudaStreamNonBlocking);
        cudaEventCreateWithFlags(&evStart, cudaEventDisableTiming);
        cudaEventCreateWithFlags(&evH, cudaEventDisableTiming);
        cudaEventCreateWithFlags(&evA, cudaEventDisableTiming);
        cudaEventCreateWithFlags(&evB, cudaEventDisableTiming);
    }

    // Fork branch A at graph root: pack weights + big XKMQ GEMM (independent of everything else).
    cudaEventRecord(evStart, 0);
    cudaStreamWaitEvent(sA, evStart, 0);
    k_pack<<<(DD * 640 + 2 * DD * 256 + 640 + 255) / 256, 256, 0, sA>>>(Wk, Wm, Wq, bk, bm, bq, Wo1, Wo2);
    {   // XKMQ = x @ [Wk1|Wm1|Wq*invs] + [bk|bm|bq*invs]
        dim3 g(5, NN / 128);
        k_gemmT<0><<<g, 256, 0, sA>>>(NN, 600, DD, x, DD, pWcat, 640, pXKMQ, 600,
                                      pbcat, nullptr, nullptr, nullptr, nullptr);
    }
    cudaEventRecord(evA, sA);

    // Main stream: zero + edge histogram.
    k_zero<<<1024, 256>>>(ntp);
    k_edgehist<<<EE / 256, 256>>>(ei, et, ntp);
    cudaEventRecord(evH, 0);

    // Fork branch B after edgehist: CSR build.
    cudaStreamWaitEvent(sB, evH, 0);
    k_scanA<<<50, 1024, 0, sB>>>();
    k_scanB<<<1, 64, 0, sB>>>();
    k_scanC<<<50, 1024, 0, sB>>>();
    k_csrfill<<<(TOTROWS + 255) / 256, 256, 0, sB>>>(ei);
    cudaEventRecord(evB, sB);

    // Main stream: small-table chain (overlaps with branches A and B).
    k_segsum3<<<400, 128>>>(x);
    k_meanT<<<(NT1 * DD + 255) / 256, 256>>>();
    k_tables<<<NCOMBO + NTY, 256>>>(We1, be1);
    k_bnstat1p<<<DD, 128>>>();
    k_emb<<<NCOMBO + NTY, 256>>>(We2, be2, ge1, bte1);
    k_h2pre<<<NCOMBO, 256>>>(Wa1, ba1);
    k_bnstat2p<<<DD, 128>>>();
    k_Rtab<<<NCOMBO, 256>>>(Wa2, ba2, ga1, bta1);
    k_attn<<<BB, 256>>>(sent, Watt);
    k_ukum<<<BB + NTY, 256>>>(Wk, Wm);

    // Join A (XKMQ ready) before D1; join B (CSR ready) before D2.
    cudaStreamWaitEvent(0, evA, 0);
    k_D1<<<(TOTROWS + 7) / 8, 256>>>(ei, ntp);
    cudaStreamWaitEvent(0, evB, 0);
    k_D2w<<<NN / 8, 256>>>(ei, ntp);
    {   // Y1 = aggr @ Wo1 + bo1  (+ fused column stats)
        dim3 g(2, NN / 128);
        k_gemmT<1><<<g, 256>>>(NN, DD, DD, pAggr, DD, pWo1P, 256, pY1, DD,
                               bo1, nullptr, nullptr, nullptr, nullptr);
    }
    k_stat3<<<1, 256>>>();
    {   // out = relu(bn(Y1)) @ Wo2 + bo2
        dim3 g(2, NN / 128);
        k_gemmT<0><<<g, 256>>>(NN, DD, DD, pY1, DD, pWo2P, 256, out, DD,
                               bo2, pb3m, pb3r, go1, bto1);
    }
}

// round 11
// speedup vs baseline: 1.3918x; 1.0329x over previous
#include <cuda_runtime.h>
#include <math.h>
#include <stdint.h>

#define DD 200
#define NTY 4
#define NET 38
#define NT1 39
#define BB 256
#define LL 1024
#define EE 262144
#define NN 51200
#define NCOMBO 608
#define TOTROWS (EE + NN)

// f32x2 packed-math helpers
#define FMA2(d,a,b)  asm("fma.rn.f32x2 %0, %1, %2, %3;" : "=l"(d) : "l"(a), "l"(b), "l"(d))
#define PACK2(d,x,y) asm("mov.b64 %0, {%1, %2};" : "=l"(d) : "f"(x), "f"(y))
#define UNPACK2(x,y,d) asm("mov.b64 {%0, %1}, %2;" : "=f"(x), "=f"(y) : "l"(d))

#define CVT_TF32(u,f) asm("cvt.rna.tf32.f32 %0, %1;" : "=r"(u) : "f"(f))
#define MMA_TF32(c0,c1,c2,c3,a0,a1,a2,a3,b0,b1) \
  asm("mma.sync.aligned.m16n8k8.row.col.f32.tf32.tf32.f32 " \
      "{%0,%1,%2,%3},{%4,%5,%6,%7},{%8,%9},{%0,%1,%2,%3};" \
      : "+f"(c0),"+f"(c1),"+f"(c2),"+f"(c3) \
      : "r"(a0),"r"(a1),"r"(a2),"r"(a3),"r"(b0),"r"(b1))

// ------------------------- scratch -------------------------
__device__ float d_coeff[(size_t)NN * NT1];
__device__ float d_sums[NT1 * DD];
__device__ int   d_cntT[NT1];
__device__ int   d_cntE[NCOMBO];
__device__ int   d_cntN[NTY];
__device__ int   d_combo[EE];
__device__ int   d_cntSrc[NN];
__device__ int   d_dstCnt[NN];
__device__ int   d_dstOff[NN + 1];
__device__ int   d_cursor[NN];
__device__ int   d_csr[TOTROWS];
__device__ int   d_blkSum[50];
__device__ float d_meanT[NT1 * DD];
__device__ float d_preE[NCOMBO * DD];
__device__ float d_preS[NTY * DD];
__device__ float d_embE[NCOMBO * DD];
__device__ float d_embS[NTY * DD];
__device__ float d_h2[NCOMBO * DD];
__device__ float d_Rtab[NCOMBO * DD];
__device__ float d_bn1m[DD], d_bn1r[DD], d_bn2m[DD], d_bn2r[DD], d_bn3m[DD], d_bn3r[DD];
__device__ float d_upd[BB * DD];
__device__ float d_UKall[(BB + NTY) * DD];
__device__ float d_UMall[(BB + NTY) * DD];
__device__ float d_Wcat[DD * 640];
__device__ float d_bcat[640];
__device__ float d_Wo1P[DD * 256];
__device__ float d_Wo2P[DD * 256];
__device__ float d_XKMQ[(size_t)NN * 600];    // per-node [XK+bk | XM+bm | (XQ+bq)*invs]
__device__ float d_ex[(size_t)TOTROWS * 4];
__device__ float d_den[NN * 4];
__device__ float d_aggr[(size_t)NN * DD];
__device__ float d_Y1[(size_t)NN * DD];
__device__ float d_colsum[DD], d_colsum2[DD];

// ------------------------- zero init + node hist (fused) -------------------------
__global__ void k_zero(const int* __restrict__ ntp) {
    long long i0 = (long long)blockIdx.x * blockDim.x + threadIdx.x;
    long long st = (long long)gridDim.x * blockDim.x;
    for (long long i = i0; i < (long long)NT1 * NN; i += st) d_coeff[i] = 0.f;
    for (long long i = i0; i < (long long)NN * 4; i += st) d_den[i] = 0.f;
    for (long long i = i0; i < NT1 * DD; i += st) d_sums[i] = 0.f;
    for (long long i = i0; i < NCOMBO; i += st) d_cntE[i] = 0;
    for (long long i = i0; i < NT1; i += st) d_cntT[i] = 0;
    for (long long i = i0; i < NTY; i += st) d_cntN[i] = 0;
    for (long long i = i0; i < DD; i += st) { d_colsum[i] = 0.f; d_colsum2[i] = 0.f; }
    for (long long i = i0; i < NN; i += st) {
        d_cntSrc[i] = 1;
        d_dstCnt[i] = 1;
        atomicAdd(&d_cntN[ntp[i]], 1);
    }
}

// smem histograms + 4 edges/thread for atomic-chain ILP
__global__ void k_edgehist(const int* __restrict__ ei, const int* __restrict__ et,
                           const int* __restrict__ ntp) {
    __shared__ int sT[NT1];
    __shared__ int sE[NCOMBO];
    int tid = threadIdx.x;
    for (int i = tid; i < NT1; i += 256) sT[i] = 0;
    for (int i = tid; i < NCOMBO; i += 256) sE[i] = 0;
    __syncthreads();
    int e0 = blockIdx.x * 1024 + tid;
    int s[4], dd[4], t[4];
#pragma unroll
    for (int j = 0; j < 4; j++) {
        int e = e0 + j * 256;
        s[j]  = ei[e];
        dd[j] = ei[EE + e];
        t[j]  = et[e];
    }
#pragma unroll
    for (int j = 0; j < 4; j++)
        atomicAdd(&d_coeff[(size_t)dd[j] * NT1 + t[j]], 1.f);
#pragma unroll
    for (int j = 0; j < 4; j++)
        atomicAdd(&d_coeff[(size_t)s[j] * NT1 + t[j]], -1.f);
#pragma unroll
    for (int j = 0; j < 4; j++) {
        int e = e0 + j * 256;
        atomicAdd(&sT[t[j]], 1);
        int c = (t[j] << 4) | (ntp[s[j]] << 2) | ntp[dd[j]];
        d_combo[e] = c;
        atomicAdd(&sE[c], 1);
    }
#pragma unroll
    for (int j = 0; j < 4; j++) atomicAdd(&d_cntSrc[s[j]], 1);
#pragma unroll
    for (int j = 0; j < 4; j++) atomicAdd(&d_dstCnt[dd[j]], 1);
    __syncthreads();
    for (int i = tid; i < NT1; i += 256) if (sT[i]) atomicAdd(&d_cntT[i], sT[i]);
    for (int i = tid; i < NCOMBO; i += 256) if (sE[i]) atomicAdd(&d_cntE[i], sE[i]);
}

// ------------------------- dst-CSR build (3-phase parallel scan) -------------------------
__global__ void k_scanA() {
    __shared__ int sm[1024];
    int tid = threadIdx.x;
    sm[tid] = d_dstCnt[blockIdx.x * 1024 + tid];
    __syncthreads();
    for (int o = 512; o > 0; o >>= 1) {
        if (tid < o) sm[tid] += sm[tid + o];
        __syncthreads();
    }
    if (tid == 0) d_blkSum[blockIdx.x] = sm[0];
}

__global__ void k_scanB() {
    __shared__ int sm[64];
    int tid = threadIdx.x;
    int v = (tid < 50) ? d_blkSum[tid] : 0;
    sm[tid] = v;
    __syncthreads();
    for (int o = 1; o < 64; o <<= 1) {
        int t = (tid >= o) ? sm[tid - o] : 0;
        __syncthreads();
        sm[tid] += t;
        __syncthreads();
    }
    if (tid < 50) d_blkSum[tid] = sm[tid] - v;
    if (tid == 49) d_dstOff[NN] = sm[49];
}

__global__ void k_scanC() {
    __shared__ int sm[1024];
    int tid = threadIdx.x;
    int g = blockIdx.x * 1024 + tid;
    int v = d_dstCnt[g];
    sm[tid] = v;
    __syncthreads();
    for (int o = 1; o < 1024; o <<= 1) {
        int t = (tid >= o) ? sm[tid - o] : 0;
        __syncthreads();
        sm[tid] += t;
        __syncthreads();
    }
    int excl = sm[tid] - v + d_blkSum[blockIdx.x];
    d_dstOff[g] = excl;
    d_cursor[g] = excl;
}

__global__ void k_csrfill(const int* __restrict__ ei) {
    int i = blockIdx.x * blockDim.x + threadIdx.x;
    if (i >= TOTROWS) return;
    int dst = (i < EE) ? ei[EE + i] : (i - EE);
    int pos = atomicAdd(&d_cursor[dst], 1);
    d_csr[pos] = i;
}

// ------------------------- segment sums -------------------------
__global__ __launch_bounds__(128) void k_segsum3(const float* __restrict__ x) {
    __shared__ unsigned long long cf2[128][NT1];
    int tid = threadIdx.x;
    int n0 = blockIdx.x * 128;
    for (int i = tid; i < 128 * NT1; i += 128) {
        float c = d_coeff[(size_t)(n0 + i / NT1) * NT1 + (i % NT1)];
        unsigned long long c2; PACK2(c2, c, c);
        cf2[i / NT1][i % NT1] = c2;
    }
    __syncthreads();
    if (tid < 100) {
        unsigned long long acc[NT1];
#pragma unroll
        for (int t = 0; t < NT1; t++) acc[t] = 0ULL;
        for (int nn = 0; nn < 128; nn++) {
            float2 xv = *(const float2*)&x[(size_t)(n0 + nn) * DD + tid * 2];
            unsigned long long xv2; PACK2(xv2, xv.x, xv.y);
#pragma unroll
            for (int t = 0; t < NT1; t++)
                FMA2(acc[t], cf2[nn][t], xv2);
        }
#pragma unroll
        for (int t = 0; t < NT1; t++) {
            float lo, hi; UNPACK2(lo, hi, acc[t]);
            if (lo != 0.f) atomicAdd(&d_sums[t * DD + tid * 2], lo);
            if (hi != 0.f) atomicAdd(&d_sums[t * DD + tid * 2 + 1], hi);
        }
    }
}

__global__ void k_meanT() {
    int i = blockIdx.x * blockDim.x + threadIdx.x;
    if (i >= NT1 * DD) return;
    int t = i / DD;
    float c = (float)d_cntT[t];
    if (c < 1.f) c = 1.f;
    d_meanT[i] = d_sums[i] / c;
}

// ------------------------- combo tables -------------------------
__global__ void k_tables(const float* __restrict__ We1, const float* __restrict__ be1) {
    int c = blockIdx.x, d = threadIdx.x;
    if (d >= DD) return;
    if (c < NCOMBO) {
        int t = c >> 4, a = (c >> 2) & 3, b = c & 3;
        d_preE[c * DD + d] = We1[t * DD + d] + We1[(NT1 + a) * DD + d]
                           + We1[(NT1 + NTY + b) * DD + d] + be1[d];
    } else {
        int t = c - NCOMBO;
        d_preS[t * DD + d] = We1[NET * DD + d] + We1[(NT1 + t) * DD + d]
                           + We1[(NT1 + NTY + t) * DD + d] + be1[d];
    }
}

__global__ void k_bnstat1p() {
    int d = blockIdx.x, tid = threadIdx.x;
    __shared__ double rs[128], rs2[128];
    double s = 0.0, s2 = 0.0;
    for (int c = tid; c < NCOMBO; c += 128) {
        double w = (double)d_cntE[c], v = (double)d_preE[c * DD + d];
        s += w * v; s2 += w * v * v;
    }
    if (tid < NTY) {
        double w = (double)d_cntN[tid], v = (double)d_preS[tid * DD + d];
        s += w * v; s2 += w * v * v;
    }
    rs[tid] = s; rs2[tid] = s2;
    __syncthreads();
    for (int o = 64; o > 0; o >>= 1) {
        if (tid < o) { rs[tid] += rs[tid + o]; rs2[tid] += rs2[tid + o]; }
        __syncthreads();
    }
    if (tid == 0) {
        double m = rs[0] / (double)TOTROWS;
        double var = rs2[0] / (double)TOTROWS - m * m;
        d_bn1m[d] = (float)m;
        d_bn1r[d] = rsqrtf((float)var + 1e-5f);
    }
}

__global__ void k_emb(const float* __restrict__ We2, const float* __restrict__ be2,
                      const float* __restrict__ g, const float* __restrict__ bt) {
    int c = blockIdx.x, d = threadIdx.x;
    __shared__ float a[DD];
    const float* srow = (c < NCOMBO) ? &d_preE[c * DD] : &d_preS[(c - NCOMBO) * DD];
    if (d < DD) {
        float v = (srow[d] - d_bn1m[d]) * d_bn1r[d] * g[d] + bt[d];
        a[d] = fmaxf(v, 0.f);
    }
    __syncthreads();
    if (d < DD) {
        float acc = 0.f;
        for (int k = 0; k < DD; k++) acc += a[k] * We2[k * DD + d];
        float* dst = (c < NCOMBO) ? &d_embE[c * DD] : &d_embS[(c - NCOMBO) * DD];
        dst[d] = acc + be2[d];
    }
}

__global__ void k_h2pre(const float* __restrict__ Wa1, const float* __restrict__ ba1) {
    int c = blockIdx.x, d = threadIdx.x;
    __shared__ float e[DD], mt[DD];
    int t = c >> 4;
    if (d < DD) { e[d] = d_embE[c * DD + d]; mt[d] = d_meanT[t * DD + d]; }
    __syncthreads();
    if (d < DD) {
        float acc = ba1[d];
        for (int k = 0; k < DD; k++) acc += e[k] * Wa1[k * DD + d];
        for (int k = 0; k < DD; k++) acc += mt[k] * Wa1[(DD + k) * DD + d];
        d_h2[c * DD + d] = acc;
    }
}

__global__ void k_bnstat2p() {
    int d = blockIdx.x, tid = threadIdx.x;
    __shared__ double rs[128], rs2[128];
    double s = 0.0, s2 = 0.0;
    for (int c = tid; c < NCOMBO; c += 128) {
        double w = (double)d_cntE[c], v = (double)d_h2[c * DD + d];
        s += w * v; s2 += w * v * v;
    }
    rs[tid] = s; rs2[tid] = s2;
    __syncthreads();
    for (int o = 64; o > 0; o >>= 1) {
        if (tid < o) { rs[tid] += rs[tid + o]; rs2[tid] += rs2[tid + o]; }
        __syncthreads();
    }
    if (tid == 0) {
        double m = rs[0] / (double)EE;
        double var = rs2[0] / (double)EE - m * m;
        d_bn2m[d] = (float)m;
        d_bn2r[d] = rsqrtf((float)var + 1e-5f);
    }
}

__global__ void k_Rtab(const float* __restrict__ Wa2, const float* __restrict__ ba2,
                       const float* __restrict__ g, const float* __restrict__ bt) {
    int c = blockIdx.x, d = threadIdx.x;
    __shared__ float a[DD];
    if (d < DD) {
        float v = (d_h2[c * DD + d] - d_bn2m[d]) * d_bn2r[d] * g[d] + bt[d];
        a[d] = fmaxf(v, 0.f);
    }
    __syncthreads();
    if (d < DD) {
        float acc = 0.f;
        for (int k = 0; k < DD; k++) acc += a[k] * Wa2[k * DD + d];
        d_Rtab[c * DD + d] = acc + ba2[d];
    }
}

// ------------------------- fused graph attention -------------------------
__global__ __launch_bounds__(256) void k_attn(const float* __restrict__ sent,
                                              const float* __restrict__ Watt) {
    int b = blockIdx.x, tid = threadIdx.x;
    __shared__ float sv[DD], q[DD];
    __shared__ float Pb[NCOMBO], Wacc[NCOMBO];
    __shared__ float red[256];
    if (tid < DD) sv[tid] = sent[b * DD + tid];
    for (int i = tid; i < NCOMBO; i += 256) Wacc[i] = 0.f;
    __syncthreads();
    if (tid < DD) {
        float a = 0.f;
        for (int k = 0; k < DD; k++) a += sv[k] * Watt[k * DD + tid];
        q[tid] = a * 0.07071067811865475f;   // 1/sqrt(200)
    }
    __syncthreads();
    int lane = tid & 31, w = tid >> 5;
    for (int c = w; c < NCOMBO; c += 8) {
        float p = 0.f;
        for (int k = lane; k < DD; k += 32) p += q[k] * d_Rtab[c * DD + k];
        for (int o = 16; o > 0; o >>= 1) p += __shfl_down_sync(0xffffffffu, p, o);
        if (lane == 0) Pb[c] = p;
    }
    __syncthreads();
    int cid[4]; float sc[4]; float lmax = -1e30f;
#pragma unroll
    for (int j = 0; j < 4; j++) {
        int e = b * LL + tid + j * 256;
        cid[j] = d_combo[e];
        sc[j] = Pb[cid[j]];
        lmax = fmaxf(lmax, sc[j]);
    }
    red[tid] = lmax; __syncthreads();
    for (int s = 128; s > 0; s >>= 1) { if (tid < s) red[tid] = fmaxf(red[tid], red[tid + s]); __syncthreads(); }
    float bmax = red[0]; __syncthreads();
    float lsum = 0.f;
#pragma unroll
    for (int j = 0; j < 4; j++) { sc[j] = expf(sc[j] - bmax); lsum += sc[j]; }
    red[tid] = lsum; __syncthreads();
    for (int s = 128; s > 0; s >>= 1) { if (tid < s) red[tid] += red[tid + s]; __syncthreads(); }
    float inv = 1.f / red[0]; __syncthreads();
#pragma unroll
    for (int j = 0; j < 4; j++) atomicAdd(&Wacc[cid[j]], sc[j] * inv);
    __syncthreads();
    if (tid < DD) {
        float a = 0.f;
        for (int c = 0; c < NCOMBO; c++) a += Wacc[c] * d_Rtab[c * DD + tid];
        d_upd[b * DD + tid] = a;
    }
}

__global__ void k_ukum(const float* __restrict__ Wk, const float* __restrict__ Wm) {
    int id = blockIdx.x, d = threadIdx.x;
    __shared__ float s[DD];
    const float* srow = (id < BB) ? &d_upd[id * DD] : &d_embS[(id - BB) * DD];
    if (d < DD) s[d] = srow[d];
    __syncthreads();
    if (d < DD) {
        float ak = 0.f, am = 0.f;
        for (int k = 0; k < DD; k++) {
            float sv = s[k];
            ak += sv * Wk[(DD + k) * DD + d];
            am += sv * Wm[(DD + k) * DD + d];
        }
        d_UKall[id * DD + d] = ak;
        d_UMall[id * DD + d] = am;
    }
}

// ------------------------- weight packing -------------------------
__global__ void k_pack(const float* __restrict__ Wk, const float* __restrict__ Wm,
                       const float* __restrict__ Wq,
                       const float* __restrict__ bk, const float* __restrict__ bm,
                       const float* __restrict__ bq,
                       const float* __restrict__ Wo1, const float* __restrict__ Wo2) {
    const float invs = 0.1414213562373095f;   // 1/sqrt(50)
    int i = blockIdx.x * blockDim.x + threadIdx.x;
    if (i < DD * 640) {
        int k = i / 640, c = i % 640;
        float v = (c < DD) ? Wk[k * DD + c]
                : (c < 2 * DD) ? Wm[k * DD + (c - DD)]
                : (c < 3 * DD) ? Wq[k * DD + (c - 2 * DD)] * invs : 0.f;
        d_Wcat[i] = v;
        return;
    }
    int j = i - DD * 640;
    if (j < DD * 256) {
        int k = j >> 8, c = j & 255;
        d_Wo1P[j] = (c < DD) ? Wo1[k * DD + c] : 0.f;
        return;
    }
    j -= DD * 256;
    if (j < DD * 256) {
        int k = j >> 8, c = j & 255;
        d_Wo2P[j] = (c < DD) ? Wo2[k * DD + c] : 0.f;
        return;
    }
    j -= DD * 256;
    if (j < 640) {
        float v = (j < DD) ? bk[j]
                : (j < 2 * DD) ? bm[j - DD]
                : (j < 3 * DD) ? bq[j - 2 * DD] * invs : 0.f;
        d_bcat[j] = v;
    }
}

// ------------------------- tf32 GEMM: 128x128 tile, 2-stage smem pipeline -------------------------
template<int DOSTAT>
__global__ __launch_bounds__(256, 2) void k_gemmT(
    int M, int Nreal, int K,
    const float* __restrict__ A, int lda,
    const float* __restrict__ B, int ldb,
    float* __restrict__ C, int ldc,
    const float* __restrict__ bias,
    const float* __restrict__ bnm, const float* __restrict__ bnr,
    const float* __restrict__ bng, const float* __restrict__ bnb) {
    __shared__ uint32_t As[2][8][132];
    __shared__ uint32_t Bs[2][8][132];
    __shared__ float cs[128], cs2[128];
    int tid = threadIdx.x;
    int lane = tid & 31, warp = tid >> 5;
    int wm = warp >> 2, wn = warp & 3;
    int gid = lane >> 2, tg = lane & 3;
    int row0 = blockIdx.y * 128, col0 = blockIdx.x * 128;
    if (DOSTAT && tid < 128) { cs[tid] = 0.f; cs2[tid] = 0.f; }

    float acc[4][4][4];
#pragma unroll
    for (int mt = 0; mt < 4; mt++)
#pragma unroll
        for (int nt = 0; nt < 4; nt++)
#pragma unroll
            for (int r = 0; r < 4; r++) acc[mt][nt][r] = 0.f;

    int rowA = row0 + (tid >> 1);
    int kA = (tid & 1) * 4;
    int rowB = tid >> 5;
    int colB = (tid & 31) * 4;
    int m0 = wm * 64, n0 = wn * 32;
    int mrow = tid >> 1;
    int nk = K / 8;

    float4 av, bv;
    {
        av = *(const float4*)&A[(size_t)rowA * lda + kA];
        if (bnm) {
            int g = kA;
            av.x = fmaxf((av.x - bnm[g])     * bnr[g]     * bng[g]     + bnb[g],     0.f);
            av.y = fmaxf((av.y - bnm[g + 1]) * bnr[g + 1] * bng[g + 1] + bnb[g + 1], 0.f);
            av.z = fmaxf((av.z - bnm[g + 2]) * bnr[g + 2] * bng[g + 2] + bnb[g + 2], 0.f);
            av.w = fmaxf((av.w - bnm[g + 3]) * bnr[g + 3] * bng[g + 3] + bnb[g + 3], 0.f);
        }
        bv = *(const float4*)&B[(size_t)rowB * ldb + col0 + colB];
        uint32_t u0, u1, u2, u3;
        CVT_TF32(u0, av.x); CVT_TF32(u1, av.y); CVT_TF32(u2, av.z); CVT_TF32(u3, av.w);
        As[0][kA + 0][mrow] = u0; As[0][kA + 1][mrow] = u1;
        As[0][kA + 2][mrow] = u2; As[0][kA + 3][mrow] = u3;
        CVT_TF32(u0, bv.x); CVT_TF32(u1, bv.y); CVT_TF32(u2, bv.z); CVT_TF32(u3, bv.w);
        Bs[0][rowB][colB] = u0; Bs[0][rowB][colB + 1] = u1;
        Bs[0][rowB][colB + 2] = u2; Bs[0][rowB][colB + 3] = u3;
    }

    for (int kt = 0; kt < nk; kt++) {
        int cur = kt & 1;
        int nxt = cur ^ 1;
        bool has = (kt + 1 < nk);
        if (has) {
            int k0 = (kt + 1) * 8;
            av = *(const float4*)&A[(size_t)rowA * lda + k0 + kA];
            if (bnm) {
                int g = k0 + kA;
                av.x = fmaxf((av.x - bnm[g])     * bnr[g]     * bng[g]     + bnb[g],     0.f);
                av.y = fmaxf((av.y - bnm[g + 1]) * bnr[g + 1] * bng[g + 1] + bnb[g + 1], 0.f);
                av.z = fmaxf((av.z - bnm[g + 2]) * bnr[g + 2] * bng[g + 2] + bnb[g + 2], 0.f);
                av.w = fmaxf((av.w - bnm[g + 3]) * bnr[g + 3] * bng[g + 3] + bnb[g + 3], 0.f);
            }
            bv = *(const float4*)&B[(size_t)(k0 + rowB) * ldb + col0 + colB];
        }
        __syncthreads();
        if (has) {
            uint32_t u0, u1, u2, u3;
            CVT_TF32(u0, av.x); CVT_TF32(u1, av.y); CVT_TF32(u2, av.z); CVT_TF32(u3, av.w);
            As[nxt][kA + 0][mrow] = u0; As[nxt][kA + 1][mrow] = u1;
            As[nxt][kA + 2][mrow] = u2; As[nxt][kA + 3][mrow] = u3;
            CVT_TF32(u0, bv.x); CVT_TF32(u1, bv.y); CVT_TF32(u2, bv.z); CVT_TF32(u3, bv.w);
            Bs[nxt][rowB][colB] = u0; Bs[nxt][rowB][colB + 1] = u1;
            Bs[nxt][rowB][colB + 2] = u2; Bs[nxt][rowB][colB + 3] = u3;
        }
        uint32_t af[4][4], bf[4][2];
#pragma unroll
        for (int mt = 0; mt < 4; mt++) {
            int mb = m0 + mt * 16 + gid;
            af[mt][0] = As[cur][tg][mb];
            af[mt][1] = As[cur][tg][mb + 8];
            af[mt][2] = As[cur][tg + 4][mb];
            af[mt][3] = As[cur][tg + 4][mb + 8];
        }
#pragma unroll
        for (int nt = 0; nt < 4; nt++) {
            int nb = n0 + nt * 8 + gid;
            bf[nt][0] = Bs[cur][tg][nb];
            bf[nt][1] = Bs[cur][tg + 4][nb];
        }
#pragma unroll
        for (int mt = 0; mt < 4; mt++)
#pragma unroll
            for (int nt = 0; nt < 4; nt++)
                MMA_TF32(acc[mt][nt][0], acc[mt][nt][1], acc[mt][nt][2], acc[mt][nt][3],
                         af[mt][0], af[mt][1], af[mt][2], af[mt][3],
                         bf[nt][0], bf[nt][1]);
    }

    float colS[4][2], colS2[4][2];
#pragma unroll
    for (int nt = 0; nt < 4; nt++) { colS[nt][0] = colS[nt][1] = 0.f; colS2[nt][0] = colS2[nt][1] = 0.f; }
#pragma unroll
    for (int mt = 0; mt < 4; mt++) {
        int r = row0 + m0 + mt * 16 + gid;
#pragma unroll
        for (int nt = 0; nt < 4; nt++) {
            int c = col0 + n0 + nt * 8 + tg * 2;
            float b0 = (bias && c < Nreal)     ? bias[c]     : 0.f;
            float b1 = (bias && c + 1 < Nreal) ? bias[c + 1] : 0.f;
            float v0 = acc[mt][nt][0] + b0;
            float v1 = acc[mt][nt][1] + b1;
            float v2 = acc[mt][nt][2] + b0;
            float v3 = acc[mt][nt][3] + b1;
            float* cr0 = &C[(size_t)r * ldc];
            float* cr1 = &C[(size_t)(r + 8) * ldc];
            if (c < Nreal)     { cr0[c] = v0; cr1[c] = v2; }
            if (c + 1 < Nreal) { cr0[c + 1] = v1; cr1[c + 1] = v3; }
            if (DOSTAT) {
                colS[nt][0]  += v0 + v2;
                colS2[nt][0] += v0 * v0 + v2 * v2;
                colS[nt][1]  += v1 + v3;
                colS2[nt][1] += v1 * v1 + v3 * v3;
            }
        }
    }
    if (DOSTAT) {
#pragma unroll
        for (int nt = 0; nt < 4; nt++) {
#pragma unroll
            for (int p = 0; p < 2; p++) {
                float a = colS[nt][p], b = colS2[nt][p];
                for (int o = 16; o >= 4; o >>= 1) {
                    a += __shfl_down_sync(0xffffffffu, a, o);
                    b += __shfl_down_sync(0xffffffffu, b, o);
                }
                colS[nt][p] = a; colS2[nt][p] = b;
            }
        }
        __syncthreads();
        if (gid == 0) {
#pragma unroll
            for (int nt = 0; nt < 4; nt++) {
                int lc = n0 + nt * 8 + tg * 2;
                atomicAdd(&cs[lc],      colS[nt][0]);
                atomicAdd(&cs2[lc],     colS2[nt][0]);
                atomicAdd(&cs[lc + 1],  colS[nt][1]);
                atomicAdd(&cs2[lc + 1], colS2[nt][1]);
            }
        }
        __syncthreads();
        if (tid < 128) {
            int gc = col0 + tid;
            if (gc < Nreal) {
                atomicAdd(&d_colsum[gc],  cs[tid]);
                atomicAdd(&d_colsum2[gc], cs2[tid]);
            }
        }
    }
}

// ------------------------- edge attention: scores + softmax denominators -------------------------
__global__ void k_D1(const int* __restrict__ ei, const int* __restrict__ ntp) {
    int warp = (blockIdx.x * blockDim.x + threadIdx.x) >> 5;
    int lane = threadIdx.x & 31;
    if (warp >= TOTROWS) return;
    int i = warp;
    int s, dd, kidx;
    if (i < EE) { s = ei[i]; dd = ei[EE + i]; kidx = i >> 10; }
    else { int n = i - EE; s = n; dd = n; kidx = BB + ntp[n]; }
    const float* kadd = &d_UKall[kidx * DD];
    const float* qrow = &d_XKMQ[(size_t)s * 600 + 400];
    const float* krow = &d_XKMQ[(size_t)dd * 600];
    int h = lane >> 3, r = lane & 7;
    float p = 0.f;
#pragma unroll
    for (int j = 0; j < 4; j++) {
        int idx = r + 8 * j;
        if (idx < 25) {
            int d0 = h * 50 + idx * 2;
            float2 q2 = *(const float2*)(qrow + d0);
            float2 k2 = *(const float2*)(krow + d0);
            float2 a2 = *(const float2*)(kadd + d0);
            p += q2.x * (k2.x + a2.x) + q2.y * (k2.y + a2.y);
        }
    }
    p += __shfl_down_sync(0xffffffffu, p, 4);
    p += __shfl_down_sync(0xffffffffu, p, 2);
    p += __shfl_down_sync(0xffffffffu, p, 1);
    if (r == 0) {
        float exv = __expf(p);
        d_ex[(size_t)i * 4 + h] = exv;
        atomicAdd(&d_den[s * 4 + h], exv);
    }
}

// ------------------------- aggregation: one warp per dst node -------------------------
__global__ __launch_bounds__(256) void k_D2w(const int* __restrict__ ei,
                                             const int* __restrict__ ntp) {
    int gw = (blockIdx.x * blockDim.x + threadIdx.x) >> 5;
    int lane = threadIdx.x & 31;
    int w = threadIdx.x >> 5;
    if (gw >= NN) return;
    int n = gw;
    int beg = d_dstOff[n], end = d_dstOff[n + 1];
    __shared__ float s_al[8][16][4];
    __shared__ int s_j[8][16], s_u[8][16];
    float acc[7];
#pragma unroll
    for (int k = 0; k < 7; k++) acc[k] = 0.f;
    for (int base = beg; base < end; base += 16) {
        int cnt = min(16, end - base);
        if (lane < cnt) {
            int i = d_csr[base + lane];
            int s, j, u;
            if (i < EE) { s = ei[i]; j = s; u = i >> 10; }
            else { int nn2 = i - EE; s = nn2; j = nn2; u = BB + ntp[nn2]; }
            s_j[w][lane] = j;
            s_u[w][lane] = u;
            float csf = (float)d_cntSrc[s];
#pragma unroll
            for (int hh = 0; hh < 4; hh++)
                s_al[w][lane][hh] = __fdividef(d_ex[(size_t)i * 4 + hh], d_den[s * 4 + hh]) * csf;
        }
        __syncwarp();
        for (int r = 0; r < cnt; r++) {
            const float* mrow = &d_XKMQ[(size_t)s_j[w][r] * 600 + 200];
            const float* urow = &d_UMall[s_u[w][r] * DD];
            float a0 = s_al[w][r][0], a1 = s_al[w][r][1];
            float a2 = s_al[w][r][2], a3 = s_al[w][r][3];
#pragma unroll
            for (int k = 0; k < 7; k++) {
                int c = lane + 32 * k;
                if (c < DD) {
                    float al = c < 50 ? a0 : c < 100 ? a1 : c < 150 ? a2 : a3;
                    acc[k] += al * (mrow[c] + urow[c]);
                }
            }
        }
        __syncwarp();
    }
#pragma unroll
    for (int k = 0; k < 7; k++) {
        int c = lane + 32 * k;
        if (c < DD) d_aggr[(size_t)n * DD + c] = acc[k];
    }
}

__global__ void k_stat3() {
    int d = threadIdx.x;
    if (d >= DD) return;
    float m = d_colsum[d] / (float)NN;
    float var = d_colsum2[d] / (float)NN - m * m;
    d_bn3m[d] = m;
    d_bn3r[d] = rsqrtf(var + 1e-5f);
}

// ------------------------- launch (forked graph: 4-way overlap) -------------------------
extern "C" void kernel_launch(void* const* d_in, const int* in_sizes, int n_in,
                              void* d_out, int out_size) {
    const float* x    = (const float*)d_in[0];
    const float* sent = (const float*)d_in[2];
    const float* We1  = (const float*)d_in[3];
    const float* be1  = (const float*)d_in[4];
    const float* ge1  = (const float*)d_in[5];
    const float* bte1 = (const float*)d_in[6];
    const float* We2  = (const float*)d_in[7];
    const float* be2  = (const float*)d_in[8];
    const float* Wa1  = (const float*)d_in[9];
    const float* ba1  = (const float*)d_in[10];
    const float* ga1  = (const float*)d_in[11];
    const float* bta1 = (const float*)d_in[12];
    const float* Wa2  = (const float*)d_in[13];
    const float* ba2  = (const float*)d_in[14];
    const float* Watt = (const float*)d_in[15];
    const float* Wk   = (const float*)d_in[16];
    const float* bk   = (const float*)d_in[17];
    const float* Wm   = (const float*)d_in[18];
    const float* bm   = (const float*)d_in[19];
    const float* Wq   = (const float*)d_in[20];
    const float* bq   = (const float*)d_in[21];
    const float* Wo1  = (const float*)d_in[22];
    const float* bo1  = (const float*)d_in[23];
    const float* go1  = (const float*)d_in[24];
    const float* bto1 = (const float*)d_in[25];
    const float* Wo2  = (const float*)d_in[26];
    const float* bo2  = (const float*)d_in[27];
    const int* ei     = (const int*)d_in[28];
    const int* et     = (const int*)d_in[29];
    const int* ntp    = (const int*)d_in[30];
    float* out = (float*)d_out;

    void* tmp;
    cudaGetSymbolAddress(&tmp, d_Wcat);  float* pWcat = (float*)tmp;
    cudaGetSymbolAddress(&tmp, d_bcat);  float* pbcat = (float*)tmp;
    cudaGetSymbolAddress(&tmp, d_Wo1P);  float* pWo1P = (float*)tmp;
    cudaGetSymbolAddress(&tmp, d_Wo2P);  float* pWo2P = (float*)tmp;
    cudaGetSymbolAddress(&tmp, d_XKMQ);  float* pXKMQ = (float*)tmp;
    cudaGetSymbolAddress(&tmp, d_aggr);  float* pAggr = (float*)tmp;
    cudaGetSymbolAddress(&tmp, d_Y1);    float* pY1   = (float*)tmp;
    cudaGetSymbolAddress(&tmp, d_bn3m);  float* pb3m  = (float*)tmp;
    cudaGetSymbolAddress(&tmp, d_bn3r);  float* pb3r  = (float*)tmp;

    static cudaStream_t sA = nullptr, sB = nullptr, sC = nullptr;
    static cudaEvent_t evStart = nullptr, evH = nullptr, evA = nullptr, evB = nullptr, evC = nullptr;
    if (!sA) {
        cudaStreamCreateWithFlags(&sA, cudaStreamNonBlocking);
        cudaStreamCreateWithFlags(&sB, cudaStreamNonBlocking);
        cudaStreamCreateWithFlags(&sC, cudaStreamNonBlocking);
        cudaEventCreateWithFlags(&evStart, cudaEventDisableTiming);
        cudaEventCreateWithFlags(&evH, cudaEventDisableTiming);
        cudaEventCreateWithFlags(&evA, cudaEventDisableTiming);
        cudaEventCreateWithFlags(&evB, cudaEventDisableTiming);
        cudaEventCreateWithFlags(&evC, cudaEventDisableTiming);
    }

    // Fork branch A at graph root: pack weights + big XKMQ GEMM (independent of everything else).
    cudaEventRecord(evStart, 0);
    cudaStreamWaitEvent(sA, evStart, 0);
    k_pack<<<(DD * 640 + 2 * DD * 256 + 640 + 255) / 256, 256, 0, sA>>>(Wk, Wm, Wq, bk, bm, bq, Wo1, Wo2);
    {   // XKMQ = x @ [Wk1|Wm1|Wq*invs] + [bk|bm|bq*invs]
        dim3 g(5, NN / 128);
        k_gemmT<0><<<g, 256, 0, sA>>>(NN, 600, DD, x, DD, pWcat, 640, pXKMQ, 600,
                                      pbcat, nullptr, nullptr, nullptr, nullptr);
    }
    cudaEventRecord(evA, sA);

    // Main stream: zero + edge histogram.
    k_zero<<<1024, 256>>>(ntp);
    k_edgehist<<<EE / 1024, 256>>>(ei, et, ntp);
    cudaEventRecord(evH, 0);

    // Fork branch B after edgehist: CSR build.
    cudaStreamWaitEvent(sB, evH, 0);
    k_scanA<<<50, 1024, 0, sB>>>();
    k_scanB<<<1, 64, 0, sB>>>();
    k_scanC<<<50, 1024, 0, sB>>>();
    k_csrfill<<<(TOTROWS + 255) / 256, 256, 0, sB>>>(ei);
    cudaEventRecord(evB, sB);

    // Fork branch C after edgehist: combo tables + BN1 + emb (independent of segsum).
    cudaStreamWaitEvent(sC, evH, 0);
    k_tables<<<NCOMBO + NTY, 256, 0, sC>>>(We1, be1);
    k_bnstat1p<<<DD, 128, 0, sC>>>();
    k_emb<<<NCOMBO + NTY, 256, 0, sC>>>(We2, be2, ge1, bte1);
    cudaEventRecord(evC, sC);

    // Main stream: segment sums (overlaps with A, B, C).
    k_segsum3<<<400, 128>>>(x);
    k_meanT<<<(NT1 * DD + 255) / 256, 256>>>();

    // Join C (embE/embS ready), then rest of the table chain.
    cudaStreamWaitEvent(0, evC, 0);
    k_h2pre<<<NCOMBO, 256>>>(Wa1, ba1);
    k_bnstat2p<<<DD, 128>>>();
    k_Rtab<<<NCOMBO, 256>>>(Wa2, ba2, ga1, bta1);
    k_attn<<<BB, 256>>>(sent, Watt);
    k_ukum<<<BB + NTY, 256>>>(Wk, Wm);

    // Join A (XKMQ ready) before D1; join B (CSR ready) before D2.
    cudaStreamWaitEvent(0, evA, 0);
    k_D1<<<(TOTROWS + 7) / 8, 256>>>(ei, ntp);
    cudaStreamWaitEvent(0, evB, 0);
    k_D2w<<<NN / 8, 256>>>(ei, ntp);
    {   // Y1 = aggr @ Wo1 + bo1  (+ fused column stats)
        dim3 g(2, NN / 128);
        k_gemmT<1><<<g, 256>>>(NN, DD, DD, pAggr, DD, pWo1P, 256, pY1, DD,
                               bo1, nullptr, nullptr, nullptr, nullptr);
    }
    k_stat3<<<1, 256>>>();
    {   // out = relu(bn(Y1)) @ Wo2 + bo2
        dim3 g(2, NN / 128);
        k_gemmT<0><<<g, 256>>>(NN, DD, DD, pY1, DD, pWo2P, 256, out, DD,
                               bo2, pb3m, pb3r, go1, bto1);
    }
}